// round 1
// baseline (speedup 1.0000x reference)
#include <cuda_runtime.h>
#include <math.h>
#include <stdint.h>

// Problem dims (fixed by the dataset)
#define B_   4
#define N_   512
#define C_   1024
#define HID_ 4096
#define NH_  16
#define D_   64
#define R_   (B_*N_)     // 2048 rows
#define EPS_ 1e-5f

// ---------------- scratch (device globals: no allocation allowed) ----------
__device__ float g_xb[R_*C_];
__device__ float g_yb[R_*C_];
__device__ float g_na[R_*C_];
__device__ float g_nb[R_*C_];
__device__ float g_ob[R_*C_];
__device__ float g_sc[B_*NH_*N_*N_];   // 16.78M floats (attention probs)
__device__ float g_hb[R_*HID_];        // MLP hidden

// ---------------- LayerNorm ----------------
// one block per row (C=1024), 256 threads
__global__ void ln_kernel(const float* __restrict__ in, float* __restrict__ out,
                          const float* __restrict__ g, const float* __restrict__ b,
                          const int* guard) {
    if (guard && !guard[0]) return;
    int row = blockIdx.x;
    const float* x = in + (size_t)row * C_;
    float* y = out + (size_t)row * C_;
    float s = 0.f, ss = 0.f;
    for (int i = threadIdx.x; i < C_; i += 256) {
        float v = x[i];
        s += v; ss += v * v;
    }
    __shared__ float red[16];
    for (int o = 16; o; o >>= 1) {
        s  += __shfl_down_sync(0xffffffffu, s, o);
        ss += __shfl_down_sync(0xffffffffu, ss, o);
    }
    int wid = threadIdx.x >> 5, lid = threadIdx.x & 31;
    if (!lid) { red[wid] = s; red[wid + 8] = ss; }
    __syncthreads();
    float mean, rstd;
    {
        float a = 0.f, c2 = 0.f;
        #pragma unroll
        for (int i = 0; i < 8; i++) { a += red[i]; c2 += red[i + 8]; }
        mean = a * (1.0f / C_);
        float var = c2 * (1.0f / C_) - mean * mean;
        rstd = rsqrtf(var + EPS_);
    }
    for (int i = threadIdx.x; i < C_; i += 256) {
        y[i] = (x[i] - mean) * rstd * g[i] + b[i];
    }
}

// ---------------- generic NN GEMM, 64x64x16 tile, 4x4/thread --------------
// C[M,N] = epi(A[M,K] @ B[K,N]); row-major; lda=K, ldb=N, ldc=N
// EPI 1: C = res + acc + bias[n]        (residual add; res may alias C)
// EPI 2: C = gelu_exact(acc + bias[n])
template <int EPI>
__global__ void gemm64(const float* __restrict__ A, const float* __restrict__ Bm,
                       float* __restrict__ C, const float* __restrict__ bias,
                       const float* __restrict__ res,
                       int M, int N, int K, const int* guard) {
    if (guard && !guard[0]) return;
    __shared__ float As[16][64];
    __shared__ float Bs[16][64];
    const int bm = blockIdx.y * 64, bn = blockIdx.x * 64;
    const int tid = threadIdx.x;
    const int tx = tid & 15, ty = tid >> 4;
    const int am = tid >> 2, ak = (tid & 3) * 4;   // A loader: row am, 4 k's
    const int bk = tid >> 4, bn4 = (tid & 15) * 4; // B loader: row bk, 4 n's
    const float* Ab = A + (size_t)(bm + am) * K + ak;
    const float* Bb = Bm + (size_t)bk * N + bn + bn4;
    float acc[4][4] = {};
    for (int k0 = 0; k0 < K; k0 += 16) {
        float4 av = *(const float4*)(Ab + k0);
        float4 bv = *(const float4*)(Bb + (size_t)k0 * N);
        As[ak + 0][am] = av.x; As[ak + 1][am] = av.y;
        As[ak + 2][am] = av.z; As[ak + 3][am] = av.w;
        *(float4*)&Bs[bk][bn4] = bv;
        __syncthreads();
        #pragma unroll
        for (int kk = 0; kk < 16; kk++) {
            float4 a = *(const float4*)&As[kk][ty * 4];
            float4 b = *(const float4*)&Bs[kk][tx * 4];
            float ar[4] = {a.x, a.y, a.z, a.w};
            float br[4] = {b.x, b.y, b.z, b.w};
            #pragma unroll
            for (int i = 0; i < 4; i++)
                #pragma unroll
                for (int j = 0; j < 4; j++)
                    acc[i][j] += ar[i] * br[j];
        }
        __syncthreads();
    }
    #pragma unroll
    for (int i = 0; i < 4; i++) {
        int m = bm + ty * 4 + i;
        #pragma unroll
        for (int j = 0; j < 4; j++) {
            int n = bn + tx * 4 + j;
            size_t idx = (size_t)m * N + n;
            float v = acc[i][j];
            if (EPI == 1) {
                C[idx] = res[idx] + v + bias[n];
            } else { // EPI == 2 : exact GELU
                v += bias[n];
                C[idx] = 0.5f * v * (1.0f + erff(v * 0.70710678118654752f));
            }
        }
    }
}

// ---------------- attention scores: S[bh,n,s] = scale * Q_h[n,:]·K_h[s,:] ---
// D=64 fits entirely in one smem tile; grid (S/64, N/64, B*NH)
__global__ void scores_kernel(const float* __restrict__ Q, const float* __restrict__ Kv,
                              float* __restrict__ S, const int* guard) {
    if (guard && !guard[0]) return;
    const int bh = blockIdx.z, b = bh >> 4, h = bh & 15;
    const int n0 = blockIdx.y * 64, s0 = blockIdx.x * 64;
    const float* Qb = Q  + (size_t)b * N_ * C_ + h * D_;
    const float* Kb = Kv + (size_t)b * N_ * C_ + h * D_;
    __shared__ float Qs[64][64];  // [d][n]
    __shared__ float Ks[64][64];  // [d][s]
    const int tid = threadIdx.x;
    const int r = tid >> 2, c0 = (tid & 3) * 4;
    #pragma unroll
    for (int q = 0; q < 4; q++) {
        int d = c0 + q * 16;
        float4 v = *(const float4*)(Qb + (size_t)(n0 + r) * C_ + d);
        Qs[d][r] = v.x; Qs[d + 1][r] = v.y; Qs[d + 2][r] = v.z; Qs[d + 3][r] = v.w;
        float4 w = *(const float4*)(Kb + (size_t)(s0 + r) * C_ + d);
        Ks[d][r] = w.x; Ks[d + 1][r] = w.y; Ks[d + 2][r] = w.z; Ks[d + 3][r] = w.w;
    }
    __syncthreads();
    const int tx = tid & 15, ty = tid >> 4;
    float acc[4][4] = {};
    #pragma unroll 8
    for (int kk = 0; kk < 64; kk++) {
        float4 a = *(const float4*)&Qs[kk][ty * 4];
        float4 b2 = *(const float4*)&Ks[kk][tx * 4];
        float ar[4] = {a.x, a.y, a.z, a.w};
        float br[4] = {b2.x, b2.y, b2.z, b2.w};
        #pragma unroll
        for (int i = 0; i < 4; i++)
            #pragma unroll
            for (int j = 0; j < 4; j++)
                acc[i][j] += ar[i] * br[j];
    }
    float* Sb = S + (size_t)bh * N_ * N_;
    #pragma unroll
    for (int i = 0; i < 4; i++)
        #pragma unroll
        for (int j = 0; j < 4; j++)
            Sb[(size_t)(n0 + ty * 4 + i) * N_ + s0 + tx * 4 + j] = acc[i][j] * 0.125f;
}

// ---------------- row softmax over 512 (32768 rows) -------------------------
__global__ void softmax_kernel(float* __restrict__ S, const int* guard) {
    if (guard && !guard[0]) return;
    float* row = S + (size_t)blockIdx.x * N_;
    const int t = threadIdx.x;           // 256 threads, 2 elems each
    float v0 = row[t], v1 = row[t + 256];
    float m = fmaxf(v0, v1);
    __shared__ float sm[8], ssum[8];
    for (int o = 16; o; o >>= 1) m = fmaxf(m, __shfl_xor_sync(0xffffffffu, m, o));
    if ((t & 31) == 0) sm[t >> 5] = m;
    __syncthreads();
    m = sm[0];
    #pragma unroll
    for (int i = 1; i < 8; i++) m = fmaxf(m, sm[i]);
    float e0 = expf(v0 - m), e1 = expf(v1 - m);
    float s = e0 + e1;
    for (int o = 16; o; o >>= 1) s += __shfl_xor_sync(0xffffffffu, s, o);
    if ((t & 31) == 0) ssum[t >> 5] = s;
    __syncthreads();
    s = 0.f;
    #pragma unroll
    for (int i = 0; i < 8; i++) s += ssum[i];
    float inv = 1.0f / s;
    row[t] = e0 * inv;
    row[t + 256] = e1 * inv;
}

// ---------------- AV: O_h[n,d] = sum_s P[bh,n,s] * V_h[s,d] -----------------
// M=512(n) x N=64(d), K=512(s); grid (1, N/64, B*NH)
__global__ void av_kernel(const float* __restrict__ P, const float* __restrict__ V,
                          float* __restrict__ O, const int* guard) {
    if (guard && !guard[0]) return;
    const int bh = blockIdx.z, b = bh >> 4, h = bh & 15;
    const int n0 = blockIdx.y * 64;
    const float* Pb = P + (size_t)bh * N_ * N_;
    const float* Vb = V + (size_t)b * N_ * C_ + h * D_;
    float* Ob = O + (size_t)b * N_ * C_ + h * D_;
    __shared__ float As[16][64];
    __shared__ float Bs[16][64];
    const int tid = threadIdx.x;
    const int tx = tid & 15, ty = tid >> 4;
    const int am = tid >> 2, ak = (tid & 3) * 4;
    const int bk = tid >> 4, bn4 = (tid & 15) * 4;
    float acc[4][4] = {};
    for (int k0 = 0; k0 < N_; k0 += 16) {
        float4 av = *(const float4*)(Pb + (size_t)(n0 + am) * N_ + ak + k0);
        float4 bv = *(const float4*)(Vb + (size_t)(bk + k0) * C_ + bn4);
        As[ak + 0][am] = av.x; As[ak + 1][am] = av.y;
        As[ak + 2][am] = av.z; As[ak + 3][am] = av.w;
        *(float4*)&Bs[bk][bn4] = bv;
        __syncthreads();
        #pragma unroll
        for (int kk = 0; kk < 16; kk++) {
            float4 a = *(const float4*)&As[kk][ty * 4];
            float4 b2 = *(const float4*)&Bs[kk][tx * 4];
            float ar[4] = {a.x, a.y, a.z, a.w};
            float br[4] = {b2.x, b2.y, b2.z, b2.w};
            #pragma unroll
            for (int i = 0; i < 4; i++)
                #pragma unroll
                for (int j = 0; j < 4; j++)
                    acc[i][j] += ar[i] * br[j];
        }
        __syncthreads();
    }
    #pragma unroll
    for (int i = 0; i < 4; i++)
        #pragma unroll
        for (int j = 0; j < 4; j++)
            Ob[(size_t)(n0 + ty * 4 + i) * C_ + tx * 4 + j] = acc[i][j];
}

// ---------------- host-side orchestration ----------------------------------
struct Weights {
    const float *n1g, *n1b, *n2g, *n2b, *pw, *pb, *w1, *b1, *w2, *b2;
};

static void attn_mlp_block(float* buf,            // residual stream (in/out)
                           float* outbuf,         // where block output goes (may == buf)
                           const float* qn,       // LN'd queries
                           const float* kvn,      // LN'd keys/values
                           float* na_scratch,     // LN2 scratch
                           float* ob, float* sc, float* hb,
                           const Weights& W, const int* guard) {
    dim3 gs(8, 8, B_ * NH_);
    scores_kernel<<<gs, 256>>>(qn, kvn, sc, guard);
    softmax_kernel<<<B_ * NH_ * N_, 256>>>(sc, guard);
    dim3 ga(1, 8, B_ * NH_);
    av_kernel<<<ga, 256>>>(sc, kvn, ob, guard);
    // outbuf = buf + ob @ pw + pb
    gemm64<1><<<dim3(C_ / 64, R_ / 64), 256>>>(ob, W.pw, outbuf, W.pb, buf,
                                               R_, C_, C_, guard);
    // MLP: outbuf += gelu(ln2(outbuf) @ w1 + b1) @ w2 + b2
    ln_kernel<<<R_, 256>>>(outbuf, na_scratch, W.n2g, W.n2b, guard);
    gemm64<2><<<dim3(HID_ / 64, R_ / 64), 256>>>(na_scratch, W.w1, hb, W.b1, nullptr,
                                                 R_, HID_, C_, guard);
    gemm64<1><<<dim3(C_ / 64, R_ / 64), 256>>>(hb, W.w2, outbuf, W.b2, outbuf,
                                               R_, C_, HID_, guard);
}

extern "C" void kernel_launch(void* const* d_in, const int* in_sizes, int n_in,
                              void* d_out, int out_size) {
    const float* x   = (const float*)d_in[0];
    const float* y   = (const float*)d_in[1];
    Weights W;
    W.n1g = (const float*)d_in[2];  W.n1b = (const float*)d_in[3];
    W.n2g = (const float*)d_in[4];  W.n2b = (const float*)d_in[5];
    W.pw  = (const float*)d_in[6];  W.pb  = (const float*)d_in[7];
    W.w1  = (const float*)d_in[8];  W.b1  = (const float*)d_in[9];
    W.w2  = (const float*)d_in[10]; W.b2  = (const float*)d_in[11];
    const int* flag = (const int*)d_in[12];
    float* out = (float*)d_out;

    float *xb, *yb, *na, *nb, *ob, *sc, *hb;
    cudaGetSymbolAddress((void**)&xb, g_xb);
    cudaGetSymbolAddress((void**)&yb, g_yb);
    cudaGetSymbolAddress((void**)&na, g_na);
    cudaGetSymbolAddress((void**)&nb, g_nb);
    cudaGetSymbolAddress((void**)&ob, g_ob);
    cudaGetSymbolAddress((void**)&sc, g_sc);
    cudaGetSymbolAddress((void**)&hb, g_hb);

    const size_t bytes = (size_t)R_ * C_ * sizeof(float);
    cudaMemcpyAsync(xb, x, bytes, cudaMemcpyDeviceToDevice);
    cudaMemcpyAsync(yb, y, bytes, cudaMemcpyDeviceToDevice);

    // KEY INSIGHT: in the reference, x1/y1 never feed back into the loop —
    // only the FINAL iteration's cross block is live. So: 4 gated self-blocks
    // per stream, then exactly one cross block per stream.
    for (int it = 0; it < 4; it++) {
        // self-attn block on x (guarded by is_selfatt)
        ln_kernel<<<R_, 256>>>(xb, na, W.n1g, W.n1b, flag);
        attn_mlp_block(xb, xb, na, na, na, ob, sc, hb, W, flag);
        // self-attn block on y
        ln_kernel<<<R_, 256>>>(yb, na, W.n1g, W.n1b, flag);
        attn_mlp_block(yb, yb, na, na, na, ob, sc, hb, W, flag);
    }

    float* ox = out;                      // x1
    float* oy = out + (size_t)R_ * C_;    // y1

    // cross block (always runs)
    ln_kernel<<<R_, 256>>>(xb, na, W.n1g, W.n1b, nullptr);
    ln_kernel<<<R_, 256>>>(yb, nb, W.n1g, W.n1b, nullptr);
    // x1 = xb + attn(q=xn, kv=yn) proj + mlp   (na/nb must stay intact until
    // both attention paths have consumed them — scratch for LN2 uses ob? no,
    // attn_mlp_block reuses its na_scratch only AFTER attention is done, so
    // run the two attention+proj halves first, then the MLPs.)
    {
        dim3 gs(8, 8, B_ * NH_), ga(1, 8, B_ * NH_);
        // x side: q = na, kv = nb
        scores_kernel<<<gs, 256>>>(na, nb, sc, nullptr);
        softmax_kernel<<<B_ * NH_ * N_, 256>>>(sc, nullptr);
        av_kernel<<<ga, 256>>>(sc, nb, ob, nullptr);
        gemm64<1><<<dim3(C_ / 64, R_ / 64), 256>>>(ob, W.pw, ox, W.pb, xb,
                                                   R_, C_, C_, nullptr);
        // y side: q = nb, kv = na
        scores_kernel<<<gs, 256>>>(nb, na, sc, nullptr);
        softmax_kernel<<<B_ * NH_ * N_, 256>>>(sc, nullptr);
        av_kernel<<<ga, 256>>>(sc, na, ob, nullptr);
        gemm64<1><<<dim3(C_ / 64, R_ / 64), 256>>>(ob, W.pw, oy, W.pb, yb,
                                                   R_, C_, C_, nullptr);
        // MLP on x1
        ln_kernel<<<R_, 256>>>(ox, na, W.n2g, W.n2b, nullptr);
        gemm64<2><<<dim3(HID_ / 64, R_ / 64), 256>>>(na, W.w1, hb, W.b1, nullptr,
                                                     R_, HID_, C_, nullptr);
        gemm64<1><<<dim3(C_ / 64, R_ / 64), 256>>>(hb, W.w2, ox, W.b2, ox,
                                                   R_, C_, HID_, nullptr);
        // MLP on y1
        ln_kernel<<<R_, 256>>>(oy, na, W.n2g, W.n2b, nullptr);
        gemm64<2><<<dim3(HID_ / 64, R_ / 64), 256>>>(na, W.w1, hb, W.b1, nullptr,
                                                     R_, HID_, C_, nullptr);
        gemm64<1><<<dim3(C_ / 64, R_ / 64), 256>>>(hb, W.w2, oy, W.b2, oy,
                                                   R_, C_, HID_, nullptr);
    }
}

// round 3
// speedup vs baseline: 2.1191x; 2.1191x over previous
#include <cuda_runtime.h>
#include <cuda_bf16.h>
#include <math.h>
#include <stdint.h>

// Problem dims (fixed by the dataset)
#define B_   4
#define N_   512
#define C_   1024
#define HID_ 4096
#define NH_  16
#define D_   64
#define R_   (B_*N_)     // 2048 rows
#define EPS_ 1e-5f

// ---------------- scratch (device globals: no allocation allowed) ----------
__device__ float g_xb[R_*C_];
__device__ float g_yb[R_*C_];
__device__ float g_na[R_*C_];
__device__ float g_nb[R_*C_];
__device__ float g_ob[R_*C_];
__device__ float g_sc[B_*NH_*N_*N_];   // attention probs
__device__ float g_hb[R_*HID_];        // MLP hidden
// hi/lo-split weights, packed in mma.m16n8k16 B-fragment layout
__device__ uint32_t g_pwh[C_*C_/2],   g_pwl[C_*C_/2];
__device__ uint32_t g_w1h[C_*HID_/2], g_w1l[C_*HID_/2];
__device__ uint32_t g_w2h[HID_*C_/2], g_w2l[HID_*C_/2];

// ======================= helpers =======================
#define CP_ASYNC16(sm, gp) \
    asm volatile("cp.async.cg.shared.global [%0], [%1], 16;" :: "r"(sm), "l"(gp))
#define CP_COMMIT() asm volatile("cp.async.commit_group;" ::: "memory")
#define CP_WAIT0()  asm volatile("cp.async.wait_group 0;" ::: "memory")

__device__ __forceinline__ uint32_t smem_u32(const void* p) {
    uint32_t a;
    asm("{ .reg .u64 t; cvta.to.shared.u64 t, %1; cvt.u32.u64 %0, t; }" : "=r"(a) : "l"(p));
    return a;
}

// split x into bf16 hi + bf16 lo (x ≈ hi + lo, residue ~2^-18 |x|)
__device__ __forceinline__ void splitbf(float x, uint16_t& h, uint16_t& l) {
    __nv_bfloat16 bh = __float2bfloat16_rn(x);
    float r = x - __bfloat162float(bh);
    __nv_bfloat16 bl = __float2bfloat16_rn(r);
    h = __bfloat16_as_ushort(bh);
    l = __bfloat16_as_ushort(bl);
}
__device__ __forceinline__ uint32_t pack2(uint16_t lo16, uint16_t hi16) {
    return (uint32_t)lo16 | ((uint32_t)hi16 << 16);
}

// bf16 mma: D(16x8,f32) += A(16x16) * B(16x8)
__device__ __forceinline__ void mma_bf16(float* c, const uint32_t* a, const uint32_t* b) {
    asm volatile(
        "mma.sync.aligned.m16n8k16.row.col.f32.bf16.bf16.f32 "
        "{%0,%1,%2,%3}, {%4,%5,%6,%7}, {%8,%9}, {%0,%1,%2,%3};"
        : "+f"(c[0]), "+f"(c[1]), "+f"(c[2]), "+f"(c[3])
        : "r"(a[0]), "r"(a[1]), "r"(a[2]), "r"(a[3]), "r"(b[0]), "r"(b[1]));
}

// ======================= LayerNorm =======================
__global__ void ln_kernel(const float* __restrict__ in, float* __restrict__ out,
                          const float* __restrict__ g, const float* __restrict__ b,
                          const int* guard) {
    if (guard && !guard[0]) return;
    int row = blockIdx.x;
    const float* x = in + (size_t)row * C_;
    float* y = out + (size_t)row * C_;
    float s = 0.f, ss = 0.f;
    for (int i = threadIdx.x; i < C_; i += 256) {
        float v = x[i];
        s += v; ss += v * v;
    }
    __shared__ float red[16];
    for (int o = 16; o; o >>= 1) {
        s  += __shfl_down_sync(0xffffffffu, s, o);
        ss += __shfl_down_sync(0xffffffffu, ss, o);
    }
    int wid = threadIdx.x >> 5, lid = threadIdx.x & 31;
    if (!lid) { red[wid] = s; red[wid + 8] = ss; }
    __syncthreads();
    float mean, rstd;
    {
        float a = 0.f, c2 = 0.f;
        #pragma unroll
        for (int i = 0; i < 8; i++) { a += red[i]; c2 += red[i + 8]; }
        mean = a * (1.0f / C_);
        float var = c2 * (1.0f / C_) - mean * mean;
        rstd = rsqrtf(var + EPS_);
    }
    for (int i = threadIdx.x; i < C_; i += 256) {
        y[i] = (x[i] - mean) * rstd * g[i] + b[i];
    }
}

// ========== weight prep: hi/lo split + pack into B-fragment layout =========
// W is [K][N] row-major. Packed layout (u32 units):
//   idx = ((ntile*(K/16) + ksg)*32 + lane)*2 + reg
// lane = g*4 + t (g = n%8 = col-in-tile, t = lane%4)
// reg 0: k = ksg*16 + 2t, 2t+1 ; reg 1: k += 8. Low half of u32 = lower k.
__global__ void pack_weight(const float* __restrict__ W, uint32_t* __restrict__ hiP,
                            uint32_t* __restrict__ loP, int K, int N) {
    int warp = threadIdx.x >> 5, lane = threadIdx.x & 31;
    int g = lane >> 2, t = lane & 3;
    int ktiles = K >> 4;
    int tiles = (N >> 3) * ktiles;
    for (int tile = blockIdx.x * 8 + warp; tile < tiles; tile += gridDim.x * 8) {
        int ntg = tile / ktiles, ksg = tile % ktiles;
        int n = ntg * 8 + g;
        #pragma unroll
        for (int reg = 0; reg < 2; reg++) {
            int k = ksg * 16 + 2 * t + reg * 8;
            float x0 = W[(size_t)k * N + n];
            float x1 = W[(size_t)(k + 1) * N + n];
            uint16_t h0, l0, h1, l1;
            splitbf(x0, h0, l0);
            splitbf(x1, h1, l1);
            size_t idx = ((size_t)tile * 32 + lane) * 2 + reg;
            hiP[idx] = pack2(h0, h1);
            loP[idx] = pack2(l0, l1);
        }
    }
}

// ======================= bf16-split mma GEMM =======================
// C[M,Nt] = epi(A[M,K](fp32) @ Wpacked)  via D = AhBh + AhBl + AlBh
// CTA 128x128, K-step 32, 8 warps (2M x 4N), warp tile 64x32.
// Stage layout (32KB): Ahi[0,8K) Alo[8K,16K) Bhi[16K,24K) Blo[24K,32K)
//   A frag addr: ((gmtile*2+ks)*32 + lane)*16 + reg*4   (gmtile 0..7)
//   B frag addr: ((gntile*2+ks)*32 + lane)*8  + reg*4   (gntile 0..15)
#define GM_STAGE 32768
#define GM_SMEM  (2 * GM_STAGE)

template <int EPI>
__global__ void __launch_bounds__(256, 1) gemm_mma(
    const float* __restrict__ A, const uint32_t* __restrict__ BhiP,
    const uint32_t* __restrict__ BloP, float* __restrict__ Cout,
    const float* __restrict__ bias, const float* __restrict__ res,
    int M, int Nt, int K, const int* guard)
{
    if (guard && !guard[0]) return;
    extern __shared__ __align__(16) char smc[];
    const int tid = threadIdx.x;
    const int warp = tid >> 5, lane = tid & 31;
    const int g = lane >> 2, t = lane & 3;
    const int wm = warp & 1, wn = warp >> 1;
    const int bm = blockIdx.y * 128, bn = blockIdx.x * 128;
    const uint32_t sb = smem_u32(smc);

    const int NIT = K >> 5;
    const int ktiles = K >> 4;

    // ---- A loader mapping: thread t handles row arow, 16 k's (one fragment) ----
    const int arow = tid >> 1;
    const int akb = (tid & 1) * 16;
    const int aks = (tid & 1);
    const float* Aptr = A + (size_t)(bm + arow) * K + akb;
    const int amtile = arow >> 4;
    const int ag = arow & 7;
    const int arm = (arow >> 3) & 1;
    const uint32_t arowbase = (uint32_t)((amtile * 2 + aks) * 32) * 16;

    float4 rA[4];
    auto ldA = [&](int k0) {
        #pragma unroll
        for (int q = 0; q < 4; q++) rA[q] = *(const float4*)(Aptr + k0 + q * 4);
    };
    auto stA = [&](int stage) {
        char* base = smc + stage * GM_STAGE;
        #pragma unroll
        for (int q = 0; q < 4; q++) {
            float xs[4] = {rA[q].x, rA[q].y, rA[q].z, rA[q].w};
            #pragma unroll
            for (int p = 0; p < 2; p++) {
                uint16_t h0, l0, h1, l1;
                splitbf(xs[2 * p], h0, l0);
                splitbf(xs[2 * p + 1], h1, l1);
                int kin = q * 4 + 2 * p;
                int tt = (kin & 7) >> 1;
                int rk = kin >> 3;
                uint32_t off = arowbase + (uint32_t)(ag * 4 + tt) * 16 + (uint32_t)(arm + 2 * rk) * 4;
                *(uint32_t*)(base + off) = pack2(h0, h1);
                *(uint32_t*)(base + 8192 + off) = pack2(l0, l1);
            }
        }
    };
    // ---- B loader: pure cp.async of packed fragments ----
    const int bn8 = bn >> 3;
    auto cpB = [&](int stage, int it) {
        uint32_t dstbase = sb + stage * GM_STAGE + 16384;
        int ksg0 = it * 2;
        #pragma unroll
        for (int q = 0; q < 2; q++) {
            int i = q * 256 + tid;          // 0..511
            int nt = i >> 5, j = i & 31;
            size_t srcoff = (((size_t)(bn8 + nt) * ktiles + ksg0) * 64 + (size_t)j * 4);
            CP_ASYNC16(dstbase + (uint32_t)(nt * 512 + j * 16), BhiP + srcoff);
            CP_ASYNC16(dstbase + 8192u + (uint32_t)(nt * 512 + j * 16), BloP + srcoff);
        }
    };

    float acc[4][4][4] = {};

    // ---- compute one 32-k step from a stage ----
    auto compute = [&](int stage) {
        char* base = smc + stage * GM_STAGE;
        #pragma unroll
        for (int ks = 0; ks < 2; ks++) {
            uint32_t ah[4][4], al[4][4], bh[4][2], bl[4][2];
            #pragma unroll
            for (int mt = 0; mt < 4; mt++) {
                uint32_t off = (uint32_t)(((wm * 4 + mt) * 2 + ks) * 32 + lane) * 16;
                uint4 v = *(const uint4*)(base + off);
                ah[mt][0] = v.x; ah[mt][1] = v.y; ah[mt][2] = v.z; ah[mt][3] = v.w;
                uint4 w = *(const uint4*)(base + 8192 + off);
                al[mt][0] = w.x; al[mt][1] = w.y; al[mt][2] = w.z; al[mt][3] = w.w;
            }
            #pragma unroll
            for (int nt = 0; nt < 4; nt++) {
                uint32_t off = 16384u + (uint32_t)(((wn * 4 + nt) * 2 + ks) * 32 + lane) * 8;
                uint2 v = *(const uint2*)(base + off);
                bh[nt][0] = v.x; bh[nt][1] = v.y;
                uint2 w = *(const uint2*)(base + 8192 + off);
                bl[nt][0] = w.x; bl[nt][1] = w.y;
            }
            #pragma unroll
            for (int mt = 0; mt < 4; mt++)
                #pragma unroll
                for (int nt = 0; nt < 4; nt++) {
                    mma_bf16(acc[mt][nt], ah[mt], bh[nt]);
                    mma_bf16(acc[mt][nt], ah[mt], bl[nt]);
                    mma_bf16(acc[mt][nt], al[mt], bh[nt]);
                }
        }
    };

    // ---- pipeline ----
    ldA(0);
    stA(0);
    cpB(0, 0);
    CP_COMMIT();
    CP_WAIT0();
    __syncthreads();

    for (int it = 0; it < NIT; it++) {
        const int buf = it & 1;
        const bool more = (it + 1) < NIT;
        if (more) {
            ldA((it + 1) * 32);
            cpB(buf ^ 1, it + 1);
            CP_COMMIT();
        }
        compute(buf);
        if (more) {
            stA(buf ^ 1);
            CP_WAIT0();
        }
        __syncthreads();
    }

    // ---- epilogue: regs -> global with bias / residual / GELU ----
    #pragma unroll
    for (int mt = 0; mt < 4; mt++) {
        #pragma unroll
        for (int nt = 0; nt < 4; nt++) {
            int row0 = bm + wm * 64 + mt * 16 + g;
            int col = bn + wn * 32 + nt * 8 + t * 2;
            float2 bv = *(const float2*)&bias[col];
            float v0 = acc[mt][nt][0] + bv.x;
            float v1 = acc[mt][nt][1] + bv.y;
            float v2 = acc[mt][nt][2] + bv.x;
            float v3 = acc[mt][nt][3] + bv.y;
            size_t i0 = (size_t)row0 * Nt + col;
            size_t i1 = (size_t)(row0 + 8) * Nt + col;
            if (EPI == 1) {
                float2 r0 = *(const float2*)&res[i0];
                float2 r1 = *(const float2*)&res[i1];
                v0 += r0.x; v1 += r0.y; v2 += r1.x; v3 += r1.y;
            } else {
                v0 = 0.5f * v0 * (1.0f + erff(v0 * 0.70710678118654752f));
                v1 = 0.5f * v1 * (1.0f + erff(v1 * 0.70710678118654752f));
                v2 = 0.5f * v2 * (1.0f + erff(v2 * 0.70710678118654752f));
                v3 = 0.5f * v3 * (1.0f + erff(v3 * 0.70710678118654752f));
            }
            *(float2*)&Cout[i0] = make_float2(v0, v1);
            *(float2*)&Cout[i1] = make_float2(v2, v3);
        }
    }
}

// ======================= attention (fp32 SIMT) ==================
__global__ void scores_kernel(const float* __restrict__ Q, const float* __restrict__ Kv,
                              float* __restrict__ S, const int* guard) {
    if (guard && !guard[0]) return;
    const int bh = blockIdx.z, b = bh >> 4, h = bh & 15;
    const int n0 = blockIdx.y * 64, s0 = blockIdx.x * 64;
    const float* Qb = Q  + (size_t)b * N_ * C_ + h * D_;
    const float* Kb = Kv + (size_t)b * N_ * C_ + h * D_;
    __shared__ float Qs[64][64];
    __shared__ float Ks[64][64];
    const int tid = threadIdx.x;
    const int r = tid >> 2, c0 = (tid & 3) * 4;
    #pragma unroll
    for (int q = 0; q < 4; q++) {
        int d = c0 + q * 16;
        float4 v = *(const float4*)(Qb + (size_t)(n0 + r) * C_ + d);
        Qs[d][r] = v.x; Qs[d + 1][r] = v.y; Qs[d + 2][r] = v.z; Qs[d + 3][r] = v.w;
        float4 w = *(const float4*)(Kb + (size_t)(s0 + r) * C_ + d);
        Ks[d][r] = w.x; Ks[d + 1][r] = w.y; Ks[d + 2][r] = w.z; Ks[d + 3][r] = w.w;
    }
    __syncthreads();
    const int tx = tid & 15, ty = tid >> 4;
    float acc[4][4] = {};
    #pragma unroll 8
    for (int kk = 0; kk < 64; kk++) {
        float4 a = *(const float4*)&Qs[kk][ty * 4];
        float4 b2 = *(const float4*)&Ks[kk][tx * 4];
        float ar[4] = {a.x, a.y, a.z, a.w};
        float br[4] = {b2.x, b2.y, b2.z, b2.w};
        #pragma unroll
        for (int i = 0; i < 4; i++)
            #pragma unroll
            for (int j = 0; j < 4; j++)
                acc[i][j] += ar[i] * br[j];
    }
    float* Sb = S + (size_t)bh * N_ * N_;
    #pragma unroll
    for (int i = 0; i < 4; i++)
        #pragma unroll
        for (int j = 0; j < 4; j++)
            Sb[(size_t)(n0 + ty * 4 + i) * N_ + s0 + tx * 4 + j] = acc[i][j] * 0.125f;
}

__global__ void softmax_kernel(float* __restrict__ S, const int* guard) {
    if (guard && !guard[0]) return;
    float* row = S + (size_t)blockIdx.x * N_;
    const int t = threadIdx.x;
    float v0 = row[t], v1 = row[t + 256];
    float m = fmaxf(v0, v1);
    __shared__ float sm[8], ssum[8];
    for (int o = 16; o; o >>= 1) m = fmaxf(m, __shfl_xor_sync(0xffffffffu, m, o));
    if ((t & 31) == 0) sm[t >> 5] = m;
    __syncthreads();
    m = sm[0];
    #pragma unroll
    for (int i = 1; i < 8; i++) m = fmaxf(m, sm[i]);
    float e0 = expf(v0 - m), e1 = expf(v1 - m);
    float s = e0 + e1;
    for (int o = 16; o; o >>= 1) s += __shfl_xor_sync(0xffffffffu, s, o);
    if ((t & 31) == 0) ssum[t >> 5] = s;
    __syncthreads();
    s = 0.f;
    #pragma unroll
    for (int i = 0; i < 8; i++) s += ssum[i];
    float inv = 1.0f / s;
    row[t] = e0 * inv;
    row[t + 256] = e1 * inv;
}

__global__ void av_kernel(const float* __restrict__ P, const float* __restrict__ V,
                          float* __restrict__ O, const int* guard) {
    if (guard && !guard[0]) return;
    const int bh = blockIdx.z, b = bh >> 4, h = bh & 15;
    const int n0 = blockIdx.y * 64;
    const float* Pb = P + (size_t)bh * N_ * N_;
    const float* Vb = V + (size_t)b * N_ * C_ + h * D_;
    float* Ob = O + (size_t)b * N_ * C_ + h * D_;
    __shared__ float As[16][64];
    __shared__ float Bs[16][64];
    const int tid = threadIdx.x;
    const int tx = tid & 15, ty = tid >> 4;
    const int am = tid >> 2, ak = (tid & 3) * 4;
    const int bk = tid >> 4, bn4 = (tid & 15) * 4;
    float acc[4][4] = {};
    for (int k0 = 0; k0 < N_; k0 += 16) {
        float4 av = *(const float4*)(Pb + (size_t)(n0 + am) * N_ + ak + k0);
        float4 bv = *(const float4*)(Vb + (size_t)(bk + k0) * C_ + bn4);
        As[ak + 0][am] = av.x; As[ak + 1][am] = av.y;
        As[ak + 2][am] = av.z; As[ak + 3][am] = av.w;
        *(float4*)&Bs[bk][bn4] = bv;
        __syncthreads();
        #pragma unroll
        for (int kk = 0; kk < 16; kk++) {
            float4 a = *(const float4*)&As[kk][ty * 4];
            float4 b2 = *(const float4*)&Bs[kk][tx * 4];
            float ar[4] = {a.x, a.y, a.z, a.w};
            float br[4] = {b2.x, b2.y, b2.z, b2.w};
            #pragma unroll
            for (int i = 0; i < 4; i++)
                #pragma unroll
                for (int j = 0; j < 4; j++)
                    acc[i][j] += ar[i] * br[j];
        }
        __syncthreads();
    }
    #pragma unroll
    for (int i = 0; i < 4; i++)
        #pragma unroll
        for (int j = 0; j < 4; j++)
            Ob[(size_t)(n0 + ty * 4 + i) * C_ + tx * 4 + j] = acc[i][j];
}

// ======================= host orchestration =======================
struct Weights {
    const float *n1g, *n1b, *n2g, *n2b, *pw, *pb, *w1, *b1, *w2, *b2;
};
struct Splits {
    uint32_t *pwh, *pwl, *w1h, *w1l, *w2h, *w2l;
};

static void attn_mlp_block(float* buf, float* outbuf,
                           const float* qn, const float* kvn,
                           float* na_scratch, float* ob, float* sc, float* hb,
                           const Weights& W, const Splits& S, const int* guard) {
    dim3 gs(8, 8, B_ * NH_);
    scores_kernel<<<gs, 256>>>(qn, kvn, sc, guard);
    softmax_kernel<<<B_ * NH_ * N_, 256>>>(sc, guard);
    dim3 ga(1, 8, B_ * NH_);
    av_kernel<<<ga, 256>>>(sc, kvn, ob, guard);
    gemm_mma<1><<<dim3(C_ / 128, R_ / 128), 256, GM_SMEM>>>(
        ob, S.pwh, S.pwl, outbuf, W.pb, buf, R_, C_, C_, guard);
    ln_kernel<<<R_, 256>>>(outbuf, na_scratch, W.n2g, W.n2b, guard);
    gemm_mma<2><<<dim3(HID_ / 128, R_ / 128), 256, GM_SMEM>>>(
        na_scratch, S.w1h, S.w1l, hb, W.b1, nullptr, R_, HID_, C_, guard);
    gemm_mma<1><<<dim3(C_ / 128, R_ / 128), 256, GM_SMEM>>>(
        hb, S.w2h, S.w2l, outbuf, W.b2, outbuf, R_, C_, HID_, guard);
}

extern "C" void kernel_launch(void* const* d_in, const int* in_sizes, int n_in,
                              void* d_out, int out_size) {
    const float* x   = (const float*)d_in[0];
    const float* y   = (const float*)d_in[1];
    Weights W;
    W.n1g = (const float*)d_in[2];  W.n1b = (const float*)d_in[3];
    W.n2g = (const float*)d_in[4];  W.n2b = (const float*)d_in[5];
    W.pw  = (const float*)d_in[6];  W.pb  = (const float*)d_in[7];
    W.w1  = (const float*)d_in[8];  W.b1  = (const float*)d_in[9];
    W.w2  = (const float*)d_in[10]; W.b2  = (const float*)d_in[11];
    const int* flag = (const int*)d_in[12];
    float* out = (float*)d_out;

    float *xb, *yb, *na, *nb, *ob, *sc, *hb;
    cudaGetSymbolAddress((void**)&xb, g_xb);
    cudaGetSymbolAddress((void**)&yb, g_yb);
    cudaGetSymbolAddress((void**)&na, g_na);
    cudaGetSymbolAddress((void**)&nb, g_nb);
    cudaGetSymbolAddress((void**)&ob, g_ob);
    cudaGetSymbolAddress((void**)&sc, g_sc);
    cudaGetSymbolAddress((void**)&hb, g_hb);
    Splits S;
    cudaGetSymbolAddress((void**)&S.pwh, g_pwh);
    cudaGetSymbolAddress((void**)&S.pwl, g_pwl);
    cudaGetSymbolAddress((void**)&S.w1h, g_w1h);
    cudaGetSymbolAddress((void**)&S.w1l, g_w1l);
    cudaGetSymbolAddress((void**)&S.w2h, g_w2h);
    cudaGetSymbolAddress((void**)&S.w2l, g_w2l);

    cudaFuncSetAttribute(gemm_mma<1>, cudaFuncAttributeMaxDynamicSharedMemorySize, GM_SMEM);
    cudaFuncSetAttribute(gemm_mma<2>, cudaFuncAttributeMaxDynamicSharedMemorySize, GM_SMEM);

    // weight prep: hi/lo split + fragment pack (runs every launch; ~25us)
    pack_weight<<<512, 256>>>(W.pw, S.pwh, S.pwl, C_, C_);
    pack_weight<<<512, 256>>>(W.w1, S.w1h, S.w1l, C_, HID_);
    pack_weight<<<512, 256>>>(W.w2, S.w2h, S.w2l, HID_, C_);

    const size_t bytes = (size_t)R_ * C_ * sizeof(float);
    cudaMemcpyAsync(xb, x, bytes, cudaMemcpyDeviceToDevice);
    cudaMemcpyAsync(yb, y, bytes, cudaMemcpyDeviceToDevice);

    // Only the FINAL iteration's cross block is live: 4 gated self-blocks per
    // stream, then exactly one cross block per stream.
    for (int it = 0; it < 4; it++) {
        ln_kernel<<<R_, 256>>>(xb, na, W.n1g, W.n1b, flag);
        attn_mlp_block(xb, xb, na, na, na, ob, sc, hb, W, S, flag);
        ln_kernel<<<R_, 256>>>(yb, na, W.n1g, W.n1b, flag);
        attn_mlp_block(yb, yb, na, na, na, ob, sc, hb, W, S, flag);
    }

    float* ox = out;                      // x1
    float* oy = out + (size_t)R_ * C_;    // y1

    ln_kernel<<<R_, 256>>>(xb, na, W.n1g, W.n1b, nullptr);
    ln_kernel<<<R_, 256>>>(yb, nb, W.n1g, W.n1b, nullptr);
    {
        dim3 gs(8, 8, B_ * NH_), ga(1, 8, B_ * NH_);
        // x side: q = na, kv = nb
        scores_kernel<<<gs, 256>>>(na, nb, sc, nullptr);
        softmax_kernel<<<B_ * NH_ * N_, 256>>>(sc, nullptr);
        av_kernel<<<ga, 256>>>(sc, nb, ob, nullptr);
        gemm_mma<1><<<dim3(C_ / 128, R_ / 128), 256, GM_SMEM>>>(
            ob, S.pwh, S.pwl, ox, W.pb, xb, R_, C_, C_, nullptr);
        // y side: q = nb, kv = na
        scores_kernel<<<gs, 256>>>(nb, na, sc, nullptr);
        softmax_kernel<<<B_ * NH_ * N_, 256>>>(sc, nullptr);
        av_kernel<<<ga, 256>>>(sc, na, ob, nullptr);
        gemm_mma<1><<<dim3(C_ / 128, R_ / 128), 256, GM_SMEM>>>(
            ob, S.pwh, S.pwl, oy, W.pb, yb, R_, C_, C_, nullptr);
        // MLP on x1
        ln_kernel<<<R_, 256>>>(ox, na, W.n2g, W.n2b, nullptr);
        gemm_mma<2><<<dim3(HID_ / 128, R_ / 128), 256, GM_SMEM>>>(
            na, S.w1h, S.w1l, hb, W.b1, nullptr, R_, HID_, C_, nullptr);
        gemm_mma<1><<<dim3(C_ / 128, R_ / 128), 256, GM_SMEM>>>(
            hb, S.w2h, S.w2l, ox, W.b2, ox, R_, C_, HID_, nullptr);
        // MLP on y1
        ln_kernel<<<R_, 256>>>(oy, na, W.n2g, W.n2b, nullptr);
        gemm_mma<2><<<dim3(HID_ / 128, R_ / 128), 256, GM_SMEM>>>(
            na, S.w1h, S.w1l, hb, W.b1, nullptr, R_, HID_, C_, nullptr);
        gemm_mma<1><<<dim3(C_ / 128, R_ / 128), 256, GM_SMEM>>>(
            hb, S.w2h, S.w2l, oy, W.b2, oy, R_, C_, HID_, nullptr);
    }
}

// round 4
// speedup vs baseline: 2.5291x; 1.1935x over previous
#include <cuda_runtime.h>
#include <cuda_bf16.h>
#include <math.h>
#include <stdint.h>

// Problem dims (fixed by the dataset)
#define B_   4
#define N_   512
#define C_   1024
#define HID_ 4096
#define NH_  16
#define D_   64
#define R_   (B_*N_)     // 2048 rows
#define EPS_ 1e-5f

// ---------------- scratch (device globals: no allocation allowed) ----------
__device__ float g_xb[R_*C_];
__device__ float g_yb[R_*C_];
__device__ float g_na[R_*C_];
__device__ float g_nb[R_*C_];
__device__ float g_ob[R_*C_];
__device__ float g_hb[R_*HID_];        // MLP hidden
// hi/lo-split weights, packed in mma.m16n8k16 B-fragment layout
__device__ uint32_t g_pwh[C_*C_/2],   g_pwl[C_*C_/2];
__device__ uint32_t g_w1h[C_*HID_/2], g_w1l[C_*HID_/2];
__device__ uint32_t g_w2h[HID_*C_/2], g_w2l[HID_*C_/2];

// ======================= helpers =======================
#define CP_ASYNC16(sm, gp) \
    asm volatile("cp.async.cg.shared.global [%0], [%1], 16;" :: "r"(sm), "l"(gp))
#define CP_COMMIT() asm volatile("cp.async.commit_group;" ::: "memory")
#define CP_WAIT0()  asm volatile("cp.async.wait_group 0;" ::: "memory")

__device__ __forceinline__ uint32_t smem_u32(const void* p) {
    uint32_t a;
    asm("{ .reg .u64 t; cvta.to.shared.u64 t, %1; cvt.u32.u64 %0, t; }" : "=r"(a) : "l"(p));
    return a;
}

// split x into bf16 hi + bf16 lo (x ≈ hi + lo, residue ~2^-18 |x|)
__device__ __forceinline__ void splitbf(float x, uint16_t& h, uint16_t& l) {
    __nv_bfloat16 bh = __float2bfloat16_rn(x);
    float r = x - __bfloat162float(bh);
    __nv_bfloat16 bl = __float2bfloat16_rn(r);
    h = __bfloat16_as_ushort(bh);
    l = __bfloat16_as_ushort(bl);
}
__device__ __forceinline__ uint32_t pack2(uint16_t lo16, uint16_t hi16) {
    return (uint32_t)lo16 | ((uint32_t)hi16 << 16);
}
__device__ __forceinline__ uint32_t packbf2(float a, float b) {
    uint16_t ha, la, hb2, lb2;
    __nv_bfloat16 x = __float2bfloat16_rn(a), y = __float2bfloat16_rn(b);
    return (uint32_t)__bfloat16_as_ushort(x) | ((uint32_t)__bfloat16_as_ushort(y) << 16);
}

// bf16 mma: D(16x8,f32) += A(16x16) * B(16x8)
__device__ __forceinline__ void mma_bf16(float* c, const uint32_t* a, const uint32_t* b) {
    asm volatile(
        "mma.sync.aligned.m16n8k16.row.col.f32.bf16.bf16.f32 "
        "{%0,%1,%2,%3}, {%4,%5,%6,%7}, {%8,%9}, {%0,%1,%2,%3};"
        : "+f"(c[0]), "+f"(c[1]), "+f"(c[2]), "+f"(c[3])
        : "r"(a[0]), "r"(a[1]), "r"(a[2]), "r"(a[3]), "r"(b[0]), "r"(b[1]));
}

// fast exp on FMA pipe (avoids MUFU throughput wall); max rel err ~8e-5
__device__ __forceinline__ float fast_exp(float x) {
    float tt = fmaxf(x * 1.4426950408889634f, -126.0f);
    float fi = floorf(tt);
    float f = tt - fi;
    float p = 0.0013333558f;
    p = fmaf(p, f, 0.0096181291f);
    p = fmaf(p, f, 0.0555041087f);
    p = fmaf(p, f, 0.2402265070f);
    p = fmaf(p, f, 0.6931471806f);
    p = fmaf(p, f, 1.0f);
    return p * __int_as_float((__float2int_rn(fi) + 127) << 23);
}

// ======================= LayerNorm =======================
__global__ void ln_kernel(const float* __restrict__ in, float* __restrict__ out,
                          const float* __restrict__ g, const float* __restrict__ b,
                          const int* guard) {
    if (guard && !guard[0]) return;
    int row = blockIdx.x;
    const float* x = in + (size_t)row * C_;
    float* y = out + (size_t)row * C_;
    float s = 0.f, ss = 0.f;
    for (int i = threadIdx.x; i < C_; i += 256) {
        float v = x[i];
        s += v; ss += v * v;
    }
    __shared__ float red[16];
    for (int o = 16; o; o >>= 1) {
        s  += __shfl_down_sync(0xffffffffu, s, o);
        ss += __shfl_down_sync(0xffffffffu, ss, o);
    }
    int wid = threadIdx.x >> 5, lid = threadIdx.x & 31;
    if (!lid) { red[wid] = s; red[wid + 8] = ss; }
    __syncthreads();
    float mean, rstd;
    {
        float a = 0.f, c2 = 0.f;
        #pragma unroll
        for (int i = 0; i < 8; i++) { a += red[i]; c2 += red[i + 8]; }
        mean = a * (1.0f / C_);
        float var = c2 * (1.0f / C_) - mean * mean;
        rstd = rsqrtf(var + EPS_);
    }
    for (int i = threadIdx.x; i < C_; i += 256) {
        y[i] = (x[i] - mean) * rstd * g[i] + b[i];
    }
}

// ========== weight prep: hi/lo split + pack into B-fragment layout =========
__global__ void pack_weight(const float* __restrict__ W, uint32_t* __restrict__ hiP,
                            uint32_t* __restrict__ loP, int K, int N) {
    int warp = threadIdx.x >> 5, lane = threadIdx.x & 31;
    int g = lane >> 2, t = lane & 3;
    int ktiles = K >> 4;
    int tiles = (N >> 3) * ktiles;
    for (int tile = blockIdx.x * 8 + warp; tile < tiles; tile += gridDim.x * 8) {
        int ntg = tile / ktiles, ksg = tile % ktiles;
        int n = ntg * 8 + g;
        #pragma unroll
        for (int reg = 0; reg < 2; reg++) {
            int k = ksg * 16 + 2 * t + reg * 8;
            float x0 = W[(size_t)k * N + n];
            float x1 = W[(size_t)(k + 1) * N + n];
            uint16_t h0, l0, h1, l1;
            splitbf(x0, h0, l0);
            splitbf(x1, h1, l1);
            size_t idx = ((size_t)tile * 32 + lane) * 2 + reg;
            hiP[idx] = pack2(h0, h1);
            loP[idx] = pack2(l0, l1);
        }
    }
}

// ======================= bf16-split mma GEMM =======================
#define GM_STAGE 32768
#define GM_SMEM  (2 * GM_STAGE)

template <int EPI>
__global__ void __launch_bounds__(256, 1) gemm_mma(
    const float* __restrict__ A, const uint32_t* __restrict__ BhiP,
    const uint32_t* __restrict__ BloP, float* __restrict__ Cout,
    const float* __restrict__ bias, const float* __restrict__ res,
    int M, int Nt, int K, const int* guard)
{
    if (guard && !guard[0]) return;
    extern __shared__ __align__(16) char smc[];
    const int tid = threadIdx.x;
    const int warp = tid >> 5, lane = tid & 31;
    const int g = lane >> 2, t = lane & 3;
    const int wm = warp & 1, wn = warp >> 1;
    const int bm = blockIdx.y * 128, bn = blockIdx.x * 128;
    const uint32_t sb = smem_u32(smc);

    const int NIT = K >> 5;
    const int ktiles = K >> 4;

    const int arow = tid >> 1;
    const int akb = (tid & 1) * 16;
    const int aks = (tid & 1);
    const float* Aptr = A + (size_t)(bm + arow) * K + akb;
    const int amtile = arow >> 4;
    const int ag = arow & 7;
    const int arm = (arow >> 3) & 1;
    const uint32_t arowbase = (uint32_t)((amtile * 2 + aks) * 32) * 16;

    float4 rA[4];
    auto ldA = [&](int k0) {
        #pragma unroll
        for (int q = 0; q < 4; q++) rA[q] = *(const float4*)(Aptr + k0 + q * 4);
    };
    auto stA = [&](int stage) {
        char* base = smc + stage * GM_STAGE;
        #pragma unroll
        for (int q = 0; q < 4; q++) {
            float xs[4] = {rA[q].x, rA[q].y, rA[q].z, rA[q].w};
            #pragma unroll
            for (int p = 0; p < 2; p++) {
                uint16_t h0, l0, h1, l1;
                splitbf(xs[2 * p], h0, l0);
                splitbf(xs[2 * p + 1], h1, l1);
                int kin = q * 4 + 2 * p;
                int tt = (kin & 7) >> 1;
                int rk = kin >> 3;
                uint32_t off = arowbase + (uint32_t)(ag * 4 + tt) * 16 + (uint32_t)(arm + 2 * rk) * 4;
                *(uint32_t*)(base + off) = pack2(h0, h1);
                *(uint32_t*)(base + 8192 + off) = pack2(l0, l1);
            }
        }
    };
    const int bn8 = bn >> 3;
    auto cpB = [&](int stage, int it) {
        uint32_t dstbase = sb + stage * GM_STAGE + 16384;
        int ksg0 = it * 2;
        #pragma unroll
        for (int q = 0; q < 2; q++) {
            int i = q * 256 + tid;
            int nt = i >> 5, j = i & 31;
            size_t srcoff = (((size_t)(bn8 + nt) * ktiles + ksg0) * 64 + (size_t)j * 4);
            CP_ASYNC16(dstbase + (uint32_t)(nt * 512 + j * 16), BhiP + srcoff);
            CP_ASYNC16(dstbase + 8192u + (uint32_t)(nt * 512 + j * 16), BloP + srcoff);
        }
    };

    float acc[4][4][4] = {};

    auto compute = [&](int stage) {
        char* base = smc + stage * GM_STAGE;
        #pragma unroll
        for (int ks = 0; ks < 2; ks++) {
            uint32_t ah[4][4], al[4][4], bh[4][2], bl[4][2];
            #pragma unroll
            for (int mt = 0; mt < 4; mt++) {
                uint32_t off = (uint32_t)(((wm * 4 + mt) * 2 + ks) * 32 + lane) * 16;
                uint4 v = *(const uint4*)(base + off);
                ah[mt][0] = v.x; ah[mt][1] = v.y; ah[mt][2] = v.z; ah[mt][3] = v.w;
                uint4 w = *(const uint4*)(base + 8192 + off);
                al[mt][0] = w.x; al[mt][1] = w.y; al[mt][2] = w.z; al[mt][3] = w.w;
            }
            #pragma unroll
            for (int nt = 0; nt < 4; nt++) {
                uint32_t off = 16384u + (uint32_t)(((wn * 4 + nt) * 2 + ks) * 32 + lane) * 8;
                uint2 v = *(const uint2*)(base + off);
                bh[nt][0] = v.x; bh[nt][1] = v.y;
                uint2 w = *(const uint2*)(base + 8192 + off);
                bl[nt][0] = w.x; bl[nt][1] = w.y;
            }
            #pragma unroll
            for (int mt = 0; mt < 4; mt++)
                #pragma unroll
                for (int nt = 0; nt < 4; nt++) {
                    mma_bf16(acc[mt][nt], ah[mt], bh[nt]);
                    mma_bf16(acc[mt][nt], ah[mt], bl[nt]);
                    mma_bf16(acc[mt][nt], al[mt], bh[nt]);
                }
        }
    };

    ldA(0);
    stA(0);
    cpB(0, 0);
    CP_COMMIT();
    CP_WAIT0();
    __syncthreads();

    for (int it = 0; it < NIT; it++) {
        const int buf = it & 1;
        const bool more = (it + 1) < NIT;
        if (more) {
            ldA((it + 1) * 32);
            cpB(buf ^ 1, it + 1);
            CP_COMMIT();
        }
        compute(buf);
        if (more) {
            stA(buf ^ 1);
            CP_WAIT0();
        }
        __syncthreads();
    }

    #pragma unroll
    for (int mt = 0; mt < 4; mt++) {
        #pragma unroll
        for (int nt = 0; nt < 4; nt++) {
            int row0 = bm + wm * 64 + mt * 16 + g;
            int col = bn + wn * 32 + nt * 8 + t * 2;
            float2 bv = *(const float2*)&bias[col];
            float v0 = acc[mt][nt][0] + bv.x;
            float v1 = acc[mt][nt][1] + bv.y;
            float v2 = acc[mt][nt][2] + bv.x;
            float v3 = acc[mt][nt][3] + bv.y;
            size_t i0 = (size_t)row0 * Nt + col;
            size_t i1 = (size_t)(row0 + 8) * Nt + col;
            if (EPI == 1) {
                float2 r0 = *(const float2*)&res[i0];
                float2 r1 = *(const float2*)&res[i1];
                v0 += r0.x; v1 += r0.y; v2 += r1.x; v3 += r1.y;
            } else {
                v0 = 0.5f * v0 * (1.0f + erff(v0 * 0.70710678118654752f));
                v1 = 0.5f * v1 * (1.0f + erff(v1 * 0.70710678118654752f));
                v2 = 0.5f * v2 * (1.0f + erff(v2 * 0.70710678118654752f));
                v3 = 0.5f * v3 * (1.0f + erff(v3 * 0.70710678118654752f));
            }
            *(float2*)&Cout[i0] = make_float2(v0, v1);
            *(float2*)&Cout[i1] = make_float2(v2, v3);
        }
    }
}

// ======================= fused flash attention (tensor cores) ===============
// grid (4 q-tiles, 64 bh), 256 threads (8 warps x 16 rows).
// Q (scaled 1/8) hi/lo A-frags persistent in smem; per 128-s chunk: K hi/lo
// B-frags, V hi/lo B-frags; S = 3-term mma; online softmax in regs; P stays
// in registers (C-layout == A-layout); O += 3-term P@V.
#define FA_QH 0
#define FA_QL 16384
#define FA_KH 32768
#define FA_KL 49152
#define FA_VH 65536
#define FA_VL 81920
#define FA_SMEM 98304

__global__ void __launch_bounds__(256, 1) fattn_kernel(
    const float* __restrict__ Q, const float* __restrict__ KV,
    float* __restrict__ O, const int* guard)
{
    if (guard && !guard[0]) return;
    extern __shared__ __align__(16) char smf[];
    const int tid = threadIdx.x, lane = tid & 31, warp = tid >> 5;
    const int g = lane >> 2, t = lane & 3;
    const int bh = blockIdx.y, b = bh >> 4, h = bh & 15;
    const int n0 = blockIdx.x * 128;
    const float* Qb = Q  + (size_t)b * N_ * C_ + h * D_;
    const float* Kb = KV + (size_t)b * N_ * C_ + h * D_;

    // ---- Q -> A-fragments (hi/lo), scaled by 1/8 ----
    {
        const int arow = tid >> 1, hf = tid & 1;
        const float* qp = Qb + (size_t)(n0 + arow) * C_ + hf * 32;
        const int mtile = arow >> 4, ag = arow & 7, arm = (arow >> 3) & 1;
        #pragma unroll
        for (int q4 = 0; q4 < 8; q4++) {
            float4 v = *(const float4*)(qp + q4 * 4);
            float xs[4] = {v.x * 0.125f, v.y * 0.125f, v.z * 0.125f, v.w * 0.125f};
            #pragma unroll
            for (int p = 0; p < 2; p++) {
                int d = hf * 32 + q4 * 4 + 2 * p;
                uint16_t h0, l0, h1, l1;
                splitbf(xs[2 * p], h0, l0);
                splitbf(xs[2 * p + 1], h1, l1);
                int kt = d >> 4, kin = d & 15;
                int tt = (kin & 7) >> 1, rk = kin >> 3;
                uint32_t idx = (uint32_t)(((mtile * 4 + kt) * 32 + ag * 4 + tt) * 4 + (arm + 2 * rk));
                *(uint32_t*)(smf + FA_QH + idx * 4) = pack2(h0, h1);
                *(uint32_t*)(smf + FA_QL + idx * 4) = pack2(l0, l1);
            }
        }
    }
    __syncthreads();

    // preload Q frags for this warp's row tile
    uint32_t qh[4][4], ql[4][4];
    #pragma unroll
    for (int kt = 0; kt < 4; kt++) {
        uint4 v = *(const uint4*)(smf + FA_QH + (size_t)(((warp * 4 + kt) * 32 + lane) * 4) * 4);
        qh[kt][0] = v.x; qh[kt][1] = v.y; qh[kt][2] = v.z; qh[kt][3] = v.w;
        uint4 w = *(const uint4*)(smf + FA_QL + (size_t)(((warp * 4 + kt) * 32 + lane) * 4) * 4);
        ql[kt][0] = w.x; ql[kt][1] = w.y; ql[kt][2] = w.z; ql[kt][3] = w.w;
    }

    float o[8][4] = {};
    float m0 = -1e30f, m1 = -1e30f, l0 = 0.f, l1 = 0.f;

    for (int ch = 0; ch < 4; ch++) {
        const int s0 = ch * 128;
        __syncthreads();  // previous chunk's readers done
        // ---- K chunk -> B-frags ----
        {
            const int r = tid >> 1, hf = tid & 1;
            const float* kp = Kb + (size_t)(s0 + r) * C_ + hf * 32;
            const int ntile = r >> 3, kg = r & 7;
            #pragma unroll
            for (int q4 = 0; q4 < 8; q4++) {
                float4 v = *(const float4*)(kp + q4 * 4);
                float xs[4] = {v.x, v.y, v.z, v.w};
                #pragma unroll
                for (int p = 0; p < 2; p++) {
                    int d = hf * 32 + q4 * 4 + 2 * p;
                    uint16_t h0, l0_, h1, l1_;
                    splitbf(xs[2 * p], h0, l0_);
                    splitbf(xs[2 * p + 1], h1, l1_);
                    int kt = d >> 4;
                    int lanef = kg * 4 + ((d & 7) >> 1);
                    int reg = ((d & 15) >= 8) ? 1 : 0;
                    uint32_t idx = (uint32_t)(((ntile * 4 + kt) * 32 + lanef) * 2 + reg);
                    *(uint32_t*)(smf + FA_KH + idx * 4) = pack2(h0, h1);
                    *(uint32_t*)(smf + FA_KL + idx * 4) = pack2(l0_, l1_);
                }
            }
        }
        // ---- V chunk -> B-frags (n=d, k=s) ----
        {
            const int sp = tid & 63, dq = tid >> 6;
            const float* vp = Kb + (size_t)(s0 + 2 * sp) * C_ + dq * 16;
            #pragma unroll
            for (int q4 = 0; q4 < 4; q4++) {
                float4 a = *(const float4*)(vp + q4 * 4);
                float4 c = *(const float4*)(vp + C_ + q4 * 4);
                float as[4] = {a.x, a.y, a.z, a.w};
                float cs[4] = {c.x, c.y, c.z, c.w};
                #pragma unroll
                for (int e = 0; e < 4; e++) {
                    int d = dq * 16 + q4 * 4 + e;
                    uint16_t h0, l0_, h1, l1_;
                    splitbf(as[e], h0, l0_);
                    splitbf(cs[e], h1, l1_);
                    int dnt = d >> 3, skt = sp >> 3;
                    int lanef = (d & 7) * 4 + (sp & 3);
                    int reg = (sp >> 2) & 1;
                    uint32_t idx = (uint32_t)(((dnt * 8 + skt) * 32 + lanef) * 2 + reg);
                    *(uint32_t*)(smf + FA_VH + idx * 4) = pack2(h0, h1);
                    *(uint32_t*)(smf + FA_VL + idx * 4) = pack2(l0_, l1_);
                }
            }
        }
        __syncthreads();

        // ---- S = Q @ K^T (3-term) ----
        float s[16][4];
        #pragma unroll
        for (int nt = 0; nt < 16; nt++) { s[nt][0] = s[nt][1] = s[nt][2] = s[nt][3] = 0.f; }
        #pragma unroll
        for (int nt = 0; nt < 16; nt++) {
            #pragma unroll
            for (int kt = 0; kt < 4; kt++) {
                uint32_t kh[2], kl[2];
                uint2 a = *(const uint2*)(smf + FA_KH + (size_t)(((nt * 4 + kt) * 32 + lane) * 2) * 4);
                kh[0] = a.x; kh[1] = a.y;
                uint2 c = *(const uint2*)(smf + FA_KL + (size_t)(((nt * 4 + kt) * 32 + lane) * 2) * 4);
                kl[0] = c.x; kl[1] = c.y;
                mma_bf16(s[nt], qh[kt], kh);
                mma_bf16(s[nt], qh[kt], kl);
                mma_bf16(s[nt], ql[kt], kh);
            }
        }

        // ---- online softmax ----
        float cm0 = -1e30f, cm1 = -1e30f;
        #pragma unroll
        for (int nt = 0; nt < 16; nt++) {
            cm0 = fmaxf(cm0, fmaxf(s[nt][0], s[nt][1]));
            cm1 = fmaxf(cm1, fmaxf(s[nt][2], s[nt][3]));
        }
        cm0 = fmaxf(cm0, __shfl_xor_sync(0xffffffffu, cm0, 1));
        cm0 = fmaxf(cm0, __shfl_xor_sync(0xffffffffu, cm0, 2));
        cm1 = fmaxf(cm1, __shfl_xor_sync(0xffffffffu, cm1, 1));
        cm1 = fmaxf(cm1, __shfl_xor_sync(0xffffffffu, cm1, 2));
        float nm0 = fmaxf(m0, cm0), nm1 = fmaxf(m1, cm1);
        float al0 = fast_exp(m0 - nm0), al1 = fast_exp(m1 - nm1);
        m0 = nm0; m1 = nm1;
        #pragma unroll
        for (int dnt = 0; dnt < 8; dnt++) {
            o[dnt][0] *= al0; o[dnt][1] *= al0;
            o[dnt][2] *= al1; o[dnt][3] *= al1;
        }
        float ls0 = 0.f, ls1 = 0.f;

        // ---- P = exp(S - m); PV mma per 16-s k-tile ----
        #pragma unroll
        for (int kt = 0; kt < 8; kt++) {
            float p00 = fast_exp(s[2 * kt][0] - m0);
            float p01 = fast_exp(s[2 * kt][1] - m0);
            float p02 = fast_exp(s[2 * kt][2] - m1);
            float p03 = fast_exp(s[2 * kt][3] - m1);
            float p10 = fast_exp(s[2 * kt + 1][0] - m0);
            float p11 = fast_exp(s[2 * kt + 1][1] - m0);
            float p12 = fast_exp(s[2 * kt + 1][2] - m1);
            float p13 = fast_exp(s[2 * kt + 1][3] - m1);
            ls0 += p00 + p01 + p10 + p11;
            ls1 += p02 + p03 + p12 + p13;
            // hi/lo A-fragments for P
            uint32_t ph[4], pl[4];
            {
                uint16_t ha, la, hb2, lb2;
                splitbf(p00, ha, la); splitbf(p01, hb2, lb2);
                ph[0] = pack2(ha, hb2); pl[0] = pack2(la, lb2);
                splitbf(p02, ha, la); splitbf(p03, hb2, lb2);
                ph[1] = pack2(ha, hb2); pl[1] = pack2(la, lb2);
                splitbf(p10, ha, la); splitbf(p11, hb2, lb2);
                ph[2] = pack2(ha, hb2); pl[2] = pack2(la, lb2);
                splitbf(p12, ha, la); splitbf(p13, hb2, lb2);
                ph[3] = pack2(ha, hb2); pl[3] = pack2(la, lb2);
            }
            #pragma unroll
            for (int dnt = 0; dnt < 8; dnt++) {
                uint32_t vh[2], vl[2];
                uint2 a = *(const uint2*)(smf + FA_VH + (size_t)(((dnt * 8 + kt) * 32 + lane) * 2) * 4);
                vh[0] = a.x; vh[1] = a.y;
                uint2 c = *(const uint2*)(smf + FA_VL + (size_t)(((dnt * 8 + kt) * 32 + lane) * 2) * 4);
                vl[0] = c.x; vl[1] = c.y;
                mma_bf16(o[dnt], ph, vh);
                mma_bf16(o[dnt], ph, vl);
                mma_bf16(o[dnt], pl, vh);
            }
        }
        ls0 += __shfl_xor_sync(0xffffffffu, ls0, 1);
        ls0 += __shfl_xor_sync(0xffffffffu, ls0, 2);
        ls1 += __shfl_xor_sync(0xffffffffu, ls1, 1);
        ls1 += __shfl_xor_sync(0xffffffffu, ls1, 2);
        l0 = l0 * al0 + ls0;
        l1 = l1 * al1 + ls1;
    }

    // ---- write O = acc / l ----
    float inv0 = 1.0f / l0, inv1 = 1.0f / l1;
    float* Ob = O + (size_t)b * N_ * C_ + h * D_;
    int row0 = n0 + warp * 16 + g;
    #pragma unroll
    for (int dnt = 0; dnt < 8; dnt++) {
        int col = dnt * 8 + 2 * t;
        *(float2*)(Ob + (size_t)row0 * C_ + col) =
            make_float2(o[dnt][0] * inv0, o[dnt][1] * inv0);
        *(float2*)(Ob + (size_t)(row0 + 8) * C_ + col) =
            make_float2(o[dnt][2] * inv1, o[dnt][3] * inv1);
    }
}

// ======================= host orchestration =======================
struct Weights {
    const float *n1g, *n1b, *n2g, *n2b, *pw, *pb, *w1, *b1, *w2, *b2;
};
struct Splits {
    uint32_t *pwh, *pwl, *w1h, *w1l, *w2h, *w2l;
};

static void attn_mlp_block(float* buf, float* outbuf,
                           const float* qn, const float* kvn,
                           float* na_scratch, float* ob, float* hb,
                           const Weights& W, const Splits& S, const int* guard) {
    fattn_kernel<<<dim3(4, 64), 256, FA_SMEM>>>(qn, kvn, ob, guard);
    gemm_mma<1><<<dim3(C_ / 128, R_ / 128), 256, GM_SMEM>>>(
        ob, S.pwh, S.pwl, outbuf, W.pb, buf, R_, C_, C_, guard);
    ln_kernel<<<R_, 256>>>(outbuf, na_scratch, W.n2g, W.n2b, guard);
    gemm_mma<2><<<dim3(HID_ / 128, R_ / 128), 256, GM_SMEM>>>(
        na_scratch, S.w1h, S.w1l, hb, W.b1, nullptr, R_, HID_, C_, guard);
    gemm_mma<1><<<dim3(C_ / 128, R_ / 128), 256, GM_SMEM>>>(
        hb, S.w2h, S.w2l, outbuf, W.b2, outbuf, R_, C_, HID_, guard);
}

extern "C" void kernel_launch(void* const* d_in, const int* in_sizes, int n_in,
                              void* d_out, int out_size) {
    const float* x   = (const float*)d_in[0];
    const float* y   = (const float*)d_in[1];
    Weights W;
    W.n1g = (const float*)d_in[2];  W.n1b = (const float*)d_in[3];
    W.n2g = (const float*)d_in[4];  W.n2b = (const float*)d_in[5];
    W.pw  = (const float*)d_in[6];  W.pb  = (const float*)d_in[7];
    W.w1  = (const float*)d_in[8];  W.b1  = (const float*)d_in[9];
    W.w2  = (const float*)d_in[10]; W.b2  = (const float*)d_in[11];
    const int* flag = (const int*)d_in[12];
    float* out = (float*)d_out;

    float *xb, *yb, *na, *nb, *ob, *hb;
    cudaGetSymbolAddress((void**)&xb, g_xb);
    cudaGetSymbolAddress((void**)&yb, g_yb);
    cudaGetSymbolAddress((void**)&na, g_na);
    cudaGetSymbolAddress((void**)&nb, g_nb);
    cudaGetSymbolAddress((void**)&ob, g_ob);
    cudaGetSymbolAddress((void**)&hb, g_hb);
    Splits S;
    cudaGetSymbolAddress((void**)&S.pwh, g_pwh);
    cudaGetSymbolAddress((void**)&S.pwl, g_pwl);
    cudaGetSymbolAddress((void**)&S.w1h, g_w1h);
    cudaGetSymbolAddress((void**)&S.w1l, g_w1l);
    cudaGetSymbolAddress((void**)&S.w2h, g_w2h);
    cudaGetSymbolAddress((void**)&S.w2l, g_w2l);

    cudaFuncSetAttribute(gemm_mma<1>, cudaFuncAttributeMaxDynamicSharedMemorySize, GM_SMEM);
    cudaFuncSetAttribute(gemm_mma<2>, cudaFuncAttributeMaxDynamicSharedMemorySize, GM_SMEM);
    cudaFuncSetAttribute(fattn_kernel, cudaFuncAttributeMaxDynamicSharedMemorySize, FA_SMEM);

    // weight prep: hi/lo split + fragment pack (runs every launch; ~25us)
    pack_weight<<<512, 256>>>(W.pw, S.pwh, S.pwl, C_, C_);
    pack_weight<<<512, 256>>>(W.w1, S.w1h, S.w1l, C_, HID_);
    pack_weight<<<512, 256>>>(W.w2, S.w2h, S.w2l, HID_, C_);

    const size_t bytes = (size_t)R_ * C_ * sizeof(float);
    cudaMemcpyAsync(xb, x, bytes, cudaMemcpyDeviceToDevice);
    cudaMemcpyAsync(yb, y, bytes, cudaMemcpyDeviceToDevice);

    // Only the FINAL iteration's cross block is live: 4 gated self-blocks per
    // stream, then exactly one cross block per stream.
    for (int it = 0; it < 4; it++) {
        ln_kernel<<<R_, 256>>>(xb, na, W.n1g, W.n1b, flag);
        attn_mlp_block(xb, xb, na, na, na, ob, hb, W, S, flag);
        ln_kernel<<<R_, 256>>>(yb, na, W.n1g, W.n1b, flag);
        attn_mlp_block(yb, yb, na, na, na, ob, hb, W, S, flag);
    }

    float* ox = out;                      // x1
    float* oy = out + (size_t)R_ * C_;    // y1

    ln_kernel<<<R_, 256>>>(xb, na, W.n1g, W.n1b, nullptr);
    ln_kernel<<<R_, 256>>>(yb, nb, W.n1g, W.n1b, nullptr);
    {
        // x side: q = na, kv = nb
        fattn_kernel<<<dim3(4, 64), 256, FA_SMEM>>>(na, nb, ob, nullptr);
        gemm_mma<1><<<dim3(C_ / 128, R_ / 128), 256, GM_SMEM>>>(
            ob, S.pwh, S.pwl, ox, W.pb, xb, R_, C_, C_, nullptr);
        // y side: q = nb, kv = na
        fattn_kernel<<<dim3(4, 64), 256, FA_SMEM>>>(nb, na, ob, nullptr);
        gemm_mma<1><<<dim3(C_ / 128, R_ / 128), 256, GM_SMEM>>>(
            ob, S.pwh, S.pwl, oy, W.pb, yb, R_, C_, C_, nullptr);
        // MLP on x1
        ln_kernel<<<R_, 256>>>(ox, na, W.n2g, W.n2b, nullptr);
        gemm_mma<2><<<dim3(HID_ / 128, R_ / 128), 256, GM_SMEM>>>(
            na, S.w1h, S.w1l, hb, W.b1, nullptr, R_, HID_, C_, nullptr);
        gemm_mma<1><<<dim3(C_ / 128, R_ / 128), 256, GM_SMEM>>>(
            hb, S.w2h, S.w2l, ox, W.b2, ox, R_, C_, HID_, nullptr);
        // MLP on y1
        ln_kernel<<<R_, 256>>>(oy, na, W.n2g, W.n2b, nullptr);
        gemm_mma<2><<<dim3(HID_ / 128, R_ / 128), 256, GM_SMEM>>>(
            na, S.w1h, S.w1l, hb, W.b1, nullptr, R_, HID_, C_, nullptr);
        gemm_mma<1><<<dim3(C_ / 128, R_ / 128), 256, GM_SMEM>>>(
            hb, S.w2h, S.w2l, oy, W.b2, oy, R_, C_, HID_, nullptr);
    }
}

// round 5
// speedup vs baseline: 3.4499x; 1.3641x over previous
#include <cuda_runtime.h>
#include <cuda_bf16.h>
#include <math.h>
#include <stdint.h>

// Problem dims (fixed by the dataset)
#define B_   4
#define N_   512
#define C_   1024
#define HID_ 4096
#define NH_  16
#define D_   64
#define R_   (B_*N_)     // 2048 rows
#define EPS_ 1e-5f

// ---------------- scratch (device globals: no allocation allowed) ----------
__device__ float g_xb[R_*C_];
__device__ float g_yb[R_*C_];
__device__ float g_na[R_*C_];     // ln1 raw out (fattn input)
__device__ float g_nb[R_*C_];
// packed (hi/lo, A-fragment layout) activations
__device__ uint32_t g_obh[R_*C_/2],  g_obl[R_*C_/2];    // fattn out -> proj A
__device__ uint32_t g_n2h[R_*C_/2],  g_n2l[R_*C_/2];    // ln2 out   -> fc1 A
__device__ uint32_t g_hbh[R_*HID_/2], g_hbl[R_*HID_/2]; // gelu out  -> fc2 A
// hi/lo-split weights, packed in mma.m16n8k16 B-fragment layout
__device__ uint32_t g_pwh[C_*C_/2],   g_pwl[C_*C_/2];
__device__ uint32_t g_w1h[C_*HID_/2], g_w1l[C_*HID_/2];
__device__ uint32_t g_w2h[HID_*C_/2], g_w2l[HID_*C_/2];

// ======================= helpers =======================
#define CP_ASYNC16(sm, gp) \
    asm volatile("cp.async.cg.shared.global [%0], [%1], 16;" :: "r"(sm), "l"(gp))
#define CP_COMMIT() asm volatile("cp.async.commit_group;" ::: "memory")
#define CP_WAIT0()  asm volatile("cp.async.wait_group 0;" ::: "memory")
#define CP_WAIT1()  asm volatile("cp.async.wait_group 1;" ::: "memory")

__device__ __forceinline__ uint32_t smem_u32(const void* p) {
    uint32_t a;
    asm("{ .reg .u64 t; cvta.to.shared.u64 t, %1; cvt.u32.u64 %0, t; }" : "=r"(a) : "l"(p));
    return a;
}

// split x into bf16 hi + bf16 lo (x ≈ hi + lo)
__device__ __forceinline__ void splitbf(float x, uint16_t& h, uint16_t& l) {
    __nv_bfloat16 bh = __float2bfloat16_rn(x);
    float r = x - __bfloat162float(bh);
    __nv_bfloat16 bl = __float2bfloat16_rn(r);
    h = __bfloat16_as_ushort(bh);
    l = __bfloat16_as_ushort(bl);
}
__device__ __forceinline__ uint32_t pack2(uint16_t lo16, uint16_t hi16) {
    return (uint32_t)lo16 | ((uint32_t)hi16 << 16);
}
// split a float pair into hi/lo packed u32s
__device__ __forceinline__ void split_pack(float a, float b, uint32_t& ph, uint32_t& pl) {
    uint16_t ha, la, hb2, lb2;
    splitbf(a, ha, la); splitbf(b, hb2, lb2);
    ph = pack2(ha, hb2); pl = pack2(la, lb2);
}

// bf16 mma: D(16x8,f32) += A(16x16) * B(16x8)
__device__ __forceinline__ void mma_bf16(float* c, const uint32_t* a, const uint32_t* b) {
    asm volatile(
        "mma.sync.aligned.m16n8k16.row.col.f32.bf16.bf16.f32 "
        "{%0,%1,%2,%3}, {%4,%5,%6,%7}, {%8,%9}, {%0,%1,%2,%3};"
        : "+f"(c[0]), "+f"(c[1]), "+f"(c[2]), "+f"(c[3])
        : "r"(a[0]), "r"(a[1]), "r"(a[2]), "r"(a[3]), "r"(b[0]), "r"(b[1]));
}

// fast exp on FMA pipe; max rel err ~8e-5
__device__ __forceinline__ float fast_exp(float x) {
    float tt = fmaxf(x * 1.4426950408889634f, -126.0f);
    float fi = floorf(tt);
    float f = tt - fi;
    float p = 0.0013333558f;
    p = fmaf(p, f, 0.0096181291f);
    p = fmaf(p, f, 0.0555041087f);
    p = fmaf(p, f, 0.2402265070f);
    p = fmaf(p, f, 0.6931471806f);
    p = fmaf(p, f, 1.0f);
    return p * __int_as_float((__float2int_rn(fi) + 127) << 23);
}

// ======================= LayerNorm (raw out, for ln1) =======================
__global__ void ln_kernel(const float* __restrict__ in, float* __restrict__ out,
                          const float* __restrict__ gm, const float* __restrict__ bt,
                          const int* guard) {
    if (guard && !guard[0]) return;
    int row = blockIdx.x;
    const float* x = in + (size_t)row * C_;
    float* y = out + (size_t)row * C_;
    float s = 0.f, ss = 0.f;
    for (int i = threadIdx.x; i < C_; i += 256) {
        float v = x[i];
        s += v; ss += v * v;
    }
    __shared__ float red[16];
    for (int o = 16; o; o >>= 1) {
        s  += __shfl_down_sync(0xffffffffu, s, o);
        ss += __shfl_down_sync(0xffffffffu, ss, o);
    }
    int wid = threadIdx.x >> 5, lid = threadIdx.x & 31;
    if (!lid) { red[wid] = s; red[wid + 8] = ss; }
    __syncthreads();
    float mean, rstd;
    {
        float a = 0.f, c2 = 0.f;
        #pragma unroll
        for (int i = 0; i < 8; i++) { a += red[i]; c2 += red[i + 8]; }
        mean = a * (1.0f / C_);
        float var = c2 * (1.0f / C_) - mean * mean;
        rstd = rsqrtf(var + EPS_);
    }
    for (int i = threadIdx.x; i < C_; i += 256) {
        y[i] = (x[i] - mean) * rstd * gm[i] + bt[i];
    }
}

// ============ LayerNorm -> packed hi/lo A-fragments (for ln2 -> fc1) =========
// 16 rows per block (one m-tile), 8 warps x 2 rows, staged via smem, coalesced.
__global__ void __launch_bounds__(256) lnp_kernel(
    const float* __restrict__ in, uint32_t* __restrict__ outH,
    uint32_t* __restrict__ outL, const float* __restrict__ gm,
    const float* __restrict__ bt, const int* guard)
{
    if (guard && !guard[0]) return;
    extern __shared__ __align__(16) char sml[];
    uint32_t* sh = (uint32_t*)sml;              // 8192 u32 (32KB)
    uint32_t* sl = (uint32_t*)(sml + 32768);
    const int w = threadIdx.x >> 5, lane = threadIdx.x & 31;

    #pragma unroll
    for (int rr = 0; rr < 2; rr++) {
        const int row = blockIdx.x * 16 + w * 2 + rr;
        const float* x = in + (size_t)row * C_;
        float4 v[8];
        float s = 0.f, ss = 0.f;
        #pragma unroll
        for (int i = 0; i < 8; i++) {
            v[i] = *(const float4*)(x + i * 128 + lane * 4);
            s += v[i].x + v[i].y + v[i].z + v[i].w;
            ss += v[i].x * v[i].x + v[i].y * v[i].y + v[i].z * v[i].z + v[i].w * v[i].w;
        }
        #pragma unroll
        for (int o = 16; o; o >>= 1) {
            s  += __shfl_xor_sync(0xffffffffu, s, o);
            ss += __shfl_xor_sync(0xffffffffu, ss, o);
        }
        float mean = s * (1.0f / C_);
        float rstd = rsqrtf(ss * (1.0f / C_) - mean * mean + EPS_);
        const int ag = row & 7, m8 = (row >> 3) & 1;
        const int kin = (lane & 3) * 4;
        const int tt0 = (kin & 7) >> 1, rk = kin >> 3;
        #pragma unroll
        for (int i = 0; i < 8; i++) {
            int c = i * 128 + lane * 4;
            float4 gv = *(const float4*)(gm + c);
            float4 bv = *(const float4*)(bt + c);
            float n0 = (v[i].x - mean) * rstd * gv.x + bv.x;
            float n1 = (v[i].y - mean) * rstd * gv.y + bv.y;
            float n2 = (v[i].z - mean) * rstd * gv.z + bv.z;
            float n3 = (v[i].w - mean) * rstd * gv.w + bv.w;
            int kt = c >> 4;
            int r = m8 + 2 * rk;
            uint32_t ph, pl;
            split_pack(n0, n1, ph, pl);
            int idx0 = (kt * 32 + ag * 4 + tt0) * 4 + r;
            sh[idx0] = ph; sl[idx0] = pl;
            split_pack(n2, n3, ph, pl);
            int idx1 = (kt * 32 + ag * 4 + tt0 + 1) * 4 + r;
            sh[idx1] = ph; sl[idx1] = pl;
        }
    }
    __syncthreads();
    // coalesced copy out: entire 32KB contiguous per array
    size_t gbase = (size_t)blockIdx.x * 8192;
    #pragma unroll
    for (int q = 0; q < 8; q++) {
        int i = q * 256 + threadIdx.x;
        *(uint4*)(outH + gbase + (size_t)i * 4) = ((const uint4*)sh)[i];
        *(uint4*)(outL + gbase + (size_t)i * 4) = ((const uint4*)sl)[i];
    }
}

// ========== weight prep: hi/lo split + pack into B-fragment layout =========
__global__ void pack_weight(const float* __restrict__ W, uint32_t* __restrict__ hiP,
                            uint32_t* __restrict__ loP, int K, int N) {
    int warp = threadIdx.x >> 5, lane = threadIdx.x & 31;
    int g = lane >> 2, t = lane & 3;
    int ktiles = K >> 4;
    int tiles = (N >> 3) * ktiles;
    for (int tile = blockIdx.x * 8 + warp; tile < tiles; tile += gridDim.x * 8) {
        int ntg = tile / ktiles, ksg = tile % ktiles;
        int n = ntg * 8 + g;
        #pragma unroll
        for (int reg = 0; reg < 2; reg++) {
            int k = ksg * 16 + 2 * t + reg * 8;
            float x0 = W[(size_t)k * N + n];
            float x1 = W[(size_t)(k + 1) * N + n];
            uint16_t h0, l0, h1, l1;
            splitbf(x0, h0, l0);
            splitbf(x1, h1, l1);
            size_t idx = ((size_t)tile * 32 + lane) * 2 + reg;
            hiP[idx] = pack2(h0, h1);
            loP[idx] = pack2(l0, l1);
        }
    }
}

// ======================= bf16-split mma GEMM (packed A + packed B) ==========
// CTA 128x128, K-step 32, 3-stage cp.async pipeline, 8 warps (2M x 4N).
// Stage layout (32KB): AH[0,8K) AL[8K,16K) BH[16K,24K) BL[24K,32K)
#define GM_STAGE 32768
#define GM_SMEM  (3 * GM_STAGE)

template <int EPI>
__global__ void __launch_bounds__(256) gemm_mma(
    const uint32_t* __restrict__ AhiP, const uint32_t* __restrict__ AloP,
    const uint32_t* __restrict__ BhiP, const uint32_t* __restrict__ BloP,
    float* __restrict__ Cout, const float* __restrict__ bias,
    const float* __restrict__ res,
    uint32_t* __restrict__ OutHi, uint32_t* __restrict__ OutLo,
    int M, int Nt, int K, const int* guard)
{
    if (guard && !guard[0]) return;
    extern __shared__ __align__(16) char smc[];
    const int tid = threadIdx.x;
    const int warp = tid >> 5, lane = tid & 31;
    const int g = lane >> 2, t = lane & 3;
    const int wm = warp & 1, wn = warp >> 1;
    const int bm = blockIdx.y * 128, bn = blockIdx.x * 128;
    const uint32_t sb = smem_u32(smc);

    const int NIT = K >> 5;
    const int ktiles = K >> 4;
    const int bm16 = bm >> 4, bn8 = bn >> 3;

    auto cpA = [&](int stage, int it) {
        uint32_t dstb = sb + stage * GM_STAGE;
        int kt0 = it * 2;
        #pragma unroll
        for (int q = 0; q < 2; q++) {
            int chunk = q * 256 + tid;       // 0..511
            int mtk = chunk >> 5, j = chunk & 31;
            int mtl = mtk >> 1, ktl = mtk & 1;
            size_t gidx = (((size_t)(bm16 + mtl) * ktiles + kt0 + ktl) * 32 + j) * 4;
            uint32_t dst = dstb + (uint32_t)(mtk * 512 + j * 16);
            CP_ASYNC16(dst, AhiP + gidx);
            CP_ASYNC16(dst + 8192u, AloP + gidx);
        }
    };
    auto cpB = [&](int stage, int it) {
        uint32_t dstb = sb + stage * GM_STAGE + 16384;
        int ksg0 = it * 2;
        #pragma unroll
        for (int q = 0; q < 2; q++) {
            int i = q * 256 + tid;
            int nt = i >> 5, j = i & 31;
            size_t srcoff = (((size_t)(bn8 + nt) * ktiles + ksg0) * 64 + (size_t)j * 4);
            uint32_t dst = dstb + (uint32_t)(nt * 512 + j * 16);
            CP_ASYNC16(dst, BhiP + srcoff);
            CP_ASYNC16(dst + 8192u, BloP + srcoff);
        }
    };

    float acc[4][4][4] = {};

    auto compute = [&](int stage) {
        char* base = smc + stage * GM_STAGE;
        #pragma unroll
        for (int ks = 0; ks < 2; ks++) {
            uint32_t ah[4][4], al[4][4], bh[4][2], bl[4][2];
            #pragma unroll
            for (int mt = 0; mt < 4; mt++) {
                uint32_t off = (uint32_t)(((wm * 4 + mt) * 2 + ks) * 32 + lane) * 16;
                uint4 v = *(const uint4*)(base + off);
                ah[mt][0] = v.x; ah[mt][1] = v.y; ah[mt][2] = v.z; ah[mt][3] = v.w;
                uint4 w = *(const uint4*)(base + 8192 + off);
                al[mt][0] = w.x; al[mt][1] = w.y; al[mt][2] = w.z; al[mt][3] = w.w;
            }
            #pragma unroll
            for (int nt = 0; nt < 4; nt++) {
                uint32_t off = 16384u + (uint32_t)(((wn * 4 + nt) * 2 + ks) * 32 + lane) * 8;
                uint2 v = *(const uint2*)(base + off);
                bh[nt][0] = v.x; bh[nt][1] = v.y;
                uint2 w = *(const uint2*)(base + 8192 + off);
                bl[nt][0] = w.x; bl[nt][1] = w.y;
            }
            #pragma unroll
            for (int mt = 0; mt < 4; mt++)
                #pragma unroll
                for (int nt = 0; nt < 4; nt++) {
                    mma_bf16(acc[mt][nt], ah[mt], bh[nt]);
                    mma_bf16(acc[mt][nt], ah[mt], bl[nt]);
                    mma_bf16(acc[mt][nt], al[mt], bh[nt]);
                }
        }
    };

    // ---- 3-stage pipeline ----
    cpA(0, 0); cpB(0, 0); CP_COMMIT();
    cpA(1, 1); cpB(1, 1); CP_COMMIT();

    int st = 0;
    for (int it = 0; it < NIT; it++) {
        if (it + 1 < NIT) { CP_WAIT1(); } else { CP_WAIT0(); }
        __syncthreads();
        if (it + 2 < NIT) {
            int ns = st + 2; if (ns >= 3) ns -= 3;
            cpA(ns, it + 2); cpB(ns, it + 2); CP_COMMIT();
        }
        compute(st);
        if (++st == 3) st = 0;
    }
    __syncthreads();

    if (EPI == 1) {
        // ---- raw out: res + acc + bias ----
        #pragma unroll
        for (int mt = 0; mt < 4; mt++) {
            #pragma unroll
            for (int nt = 0; nt < 4; nt++) {
                int row0 = bm + wm * 64 + mt * 16 + g;
                int col = bn + wn * 32 + nt * 8 + t * 2;
                float2 bv = *(const float2*)&bias[col];
                float v0 = acc[mt][nt][0] + bv.x;
                float v1 = acc[mt][nt][1] + bv.y;
                float v2 = acc[mt][nt][2] + bv.x;
                float v3 = acc[mt][nt][3] + bv.y;
                size_t i0 = (size_t)row0 * Nt + col;
                size_t i1 = (size_t)(row0 + 8) * Nt + col;
                float2 r0 = *(const float2*)&res[i0];
                float2 r1 = *(const float2*)&res[i1];
                *(float2*)&Cout[i0] = make_float2(v0 + r0.x, v1 + r0.y);
                *(float2*)&Cout[i1] = make_float2(v2 + r1.x, v3 + r1.y);
            }
        }
    } else {
        // ---- GELU -> packed hi/lo A-fragment out, staged via smem ----
        uint32_t* sh = (uint32_t*)smc;             // 8192 u32
        uint32_t* sl = (uint32_t*)(smc + 32768);
        #pragma unroll
        for (int mt = 0; mt < 4; mt++) {
            #pragma unroll
            for (int nt = 0; nt < 4; nt++) {
                int kl = wn * 32 + nt * 8 + t * 2;
                float2 bv = *(const float2*)&bias[bn + kl];
                float v0 = acc[mt][nt][0] + bv.x;
                float v1 = acc[mt][nt][1] + bv.y;
                float v2 = acc[mt][nt][2] + bv.x;
                float v3 = acc[mt][nt][3] + bv.y;
                v0 = 0.5f * v0 * (1.0f + erff(v0 * 0.70710678118654752f));
                v1 = 0.5f * v1 * (1.0f + erff(v1 * 0.70710678118654752f));
                v2 = 0.5f * v2 * (1.0f + erff(v2 * 0.70710678118654752f));
                v3 = 0.5f * v3 * (1.0f + erff(v3 * 0.70710678118654752f));
                int mtl = wm * 4 + mt;
                int ktl = kl >> 4;
                int tt = (kl & 7) >> 1;      // == t
                int rk = (kl >> 3) & 1;
                int baseI = ((mtl * 8 + ktl) * 32 + g * 4 + tt) * 4;
                uint32_t ph, pl;
                split_pack(v0, v1, ph, pl);
                sh[baseI + 2 * rk] = ph; sl[baseI + 2 * rk] = pl;
                split_pack(v2, v3, ph, pl);
                sh[baseI + 1 + 2 * rk] = ph; sl[baseI + 1 + 2 * rk] = pl;
            }
        }
        __syncthreads();
        const int ktO = Nt >> 4;
        #pragma unroll
        for (int q = 0; q < 8; q++) {
            int i = q * 256 + tid;           // 0..2047 uint4 slots
            int mtl = i >> 8, jj = i & 255;
            size_t gidx = (((size_t)(bm16 + mtl) * ktO + (bn >> 4)) * 128) + (size_t)jj * 4;
            *(uint4*)(OutHi + gidx) = ((const uint4*)sh)[i];
            *(uint4*)(OutLo + gidx) = ((const uint4*)sl)[i];
        }
    }
}

// ======================= fused flash attention (tensor cores) ===============
// grid (4 q-tiles, 64 bh), 256 threads. Output written as packed hi/lo A-frags.
#define FA_QH 0
#define FA_QL 16384
#define FA_KH 32768
#define FA_KL 49152
#define FA_VH 65536
#define FA_VL 81920
#define FA_SMEM 98304

__global__ void __launch_bounds__(256, 1) fattn_kernel(
    const float* __restrict__ Q, const float* __restrict__ KV,
    uint32_t* __restrict__ Ohi, uint32_t* __restrict__ Olo, const int* guard)
{
    if (guard && !guard[0]) return;
    extern __shared__ __align__(16) char smf[];
    const int tid = threadIdx.x, lane = tid & 31, warp = tid >> 5;
    const int g = lane >> 2, t = lane & 3;
    const int bh = blockIdx.y, b = bh >> 4, h = bh & 15;
    const int n0 = blockIdx.x * 128;
    const float* Qb = Q  + (size_t)b * N_ * C_ + h * D_;
    const float* Kb = KV + (size_t)b * N_ * C_ + h * D_;

    // ---- Q -> A-fragments (hi/lo), scaled by 1/8 ----
    {
        const int arow = tid >> 1, hf = tid & 1;
        const float* qp = Qb + (size_t)(n0 + arow) * C_ + hf * 32;
        const int mtile = arow >> 4, ag = arow & 7, arm = (arow >> 3) & 1;
        #pragma unroll
        for (int q4 = 0; q4 < 8; q4++) {
            float4 v = *(const float4*)(qp + q4 * 4);
            float xs[4] = {v.x * 0.125f, v.y * 0.125f, v.z * 0.125f, v.w * 0.125f};
            #pragma unroll
            for (int p = 0; p < 2; p++) {
                int d = hf * 32 + q4 * 4 + 2 * p;
                uint32_t ph, pl;
                split_pack(xs[2 * p], xs[2 * p + 1], ph, pl);
                int kt = d >> 4, kin = d & 15;
                int tt = (kin & 7) >> 1, rk = kin >> 3;
                uint32_t idx = (uint32_t)(((mtile * 4 + kt) * 32 + ag * 4 + tt) * 4 + (arm + 2 * rk));
                *(uint32_t*)(smf + FA_QH + idx * 4) = ph;
                *(uint32_t*)(smf + FA_QL + idx * 4) = pl;
            }
        }
    }
    __syncthreads();

    uint32_t qh[4][4], ql[4][4];
    #pragma unroll
    for (int kt = 0; kt < 4; kt++) {
        uint4 v = *(const uint4*)(smf + FA_QH + (size_t)(((warp * 4 + kt) * 32 + lane) * 4) * 4);
        qh[kt][0] = v.x; qh[kt][1] = v.y; qh[kt][2] = v.z; qh[kt][3] = v.w;
        uint4 w = *(const uint4*)(smf + FA_QL + (size_t)(((warp * 4 + kt) * 32 + lane) * 4) * 4);
        ql[kt][0] = w.x; ql[kt][1] = w.y; ql[kt][2] = w.z; ql[kt][3] = w.w;
    }

    float o[8][4] = {};
    float m0 = -1e30f, m1 = -1e30f, l0 = 0.f, l1 = 0.f;

    for (int ch = 0; ch < 4; ch++) {
        const int s0 = ch * 128;
        __syncthreads();
        // ---- K chunk -> B-frags ----
        {
            const int r = tid >> 1, hf = tid & 1;
            const float* kp = Kb + (size_t)(s0 + r) * C_ + hf * 32;
            const int ntile = r >> 3, kg = r & 7;
            #pragma unroll
            for (int q4 = 0; q4 < 8; q4++) {
                float4 v = *(const float4*)(kp + q4 * 4);
                float xs[4] = {v.x, v.y, v.z, v.w};
                #pragma unroll
                for (int p = 0; p < 2; p++) {
                    int d = hf * 32 + q4 * 4 + 2 * p;
                    uint32_t ph, pl;
                    split_pack(xs[2 * p], xs[2 * p + 1], ph, pl);
                    int kt = d >> 4;
                    int lanef = kg * 4 + ((d & 7) >> 1);
                    int reg = ((d & 15) >= 8) ? 1 : 0;
                    uint32_t idx = (uint32_t)(((ntile * 4 + kt) * 32 + lanef) * 2 + reg);
                    *(uint32_t*)(smf + FA_KH + idx * 4) = ph;
                    *(uint32_t*)(smf + FA_KL + idx * 4) = pl;
                }
            }
        }
        // ---- V chunk -> B-frags (n=d, k=s) ----
        {
            const int sp = tid & 63, dq = tid >> 6;
            const float* vp = Kb + (size_t)(s0 + 2 * sp) * C_ + dq * 16;
            #pragma unroll
            for (int q4 = 0; q4 < 4; q4++) {
                float4 a = *(const float4*)(vp + q4 * 4);
                float4 c = *(const float4*)(vp + C_ + q4 * 4);
                float as[4] = {a.x, a.y, a.z, a.w};
                float cs[4] = {c.x, c.y, c.z, c.w};
                #pragma unroll
                for (int e = 0; e < 4; e++) {
                    int d = dq * 16 + q4 * 4 + e;
                    uint32_t ph, pl;
                    split_pack(as[e], cs[e], ph, pl);
                    int dnt = d >> 3, skt = sp >> 3;
                    int lanef = (d & 7) * 4 + (sp & 3);
                    int reg = (sp >> 2) & 1;
                    uint32_t idx = (uint32_t)(((dnt * 8 + skt) * 32 + lanef) * 2 + reg);
                    *(uint32_t*)(smf + FA_VH + idx * 4) = ph;
                    *(uint32_t*)(smf + FA_VL + idx * 4) = pl;
                }
            }
        }
        __syncthreads();

        // ---- S = Q @ K^T (3-term) ----
        float s[16][4];
        #pragma unroll
        for (int nt = 0; nt < 16; nt++) { s[nt][0] = s[nt][1] = s[nt][2] = s[nt][3] = 0.f; }
        #pragma unroll
        for (int nt = 0; nt < 16; nt++) {
            #pragma unroll
            for (int kt = 0; kt < 4; kt++) {
                uint32_t kh[2], kl[2];
                uint2 a = *(const uint2*)(smf + FA_KH + (size_t)(((nt * 4 + kt) * 32 + lane) * 2) * 4);
                kh[0] = a.x; kh[1] = a.y;
                uint2 c = *(const uint2*)(smf + FA_KL + (size_t)(((nt * 4 + kt) * 32 + lane) * 2) * 4);
                kl[0] = c.x; kl[1] = c.y;
                mma_bf16(s[nt], qh[kt], kh);
                mma_bf16(s[nt], qh[kt], kl);
                mma_bf16(s[nt], ql[kt], kh);
            }
        }

        // ---- online softmax ----
        float cm0 = -1e30f, cm1 = -1e30f;
        #pragma unroll
        for (int nt = 0; nt < 16; nt++) {
            cm0 = fmaxf(cm0, fmaxf(s[nt][0], s[nt][1]));
            cm1 = fmaxf(cm1, fmaxf(s[nt][2], s[nt][3]));
        }
        cm0 = fmaxf(cm0, __shfl_xor_sync(0xffffffffu, cm0, 1));
        cm0 = fmaxf(cm0, __shfl_xor_sync(0xffffffffu, cm0, 2));
        cm1 = fmaxf(cm1, __shfl_xor_sync(0xffffffffu, cm1, 1));
        cm1 = fmaxf(cm1, __shfl_xor_sync(0xffffffffu, cm1, 2));
        float nm0 = fmaxf(m0, cm0), nm1 = fmaxf(m1, cm1);
        float al0 = fast_exp(m0 - nm0), al1 = fast_exp(m1 - nm1);
        m0 = nm0; m1 = nm1;
        #pragma unroll
        for (int dnt = 0; dnt < 8; dnt++) {
            o[dnt][0] *= al0; o[dnt][1] *= al0;
            o[dnt][2] *= al1; o[dnt][3] *= al1;
        }
        float ls0 = 0.f, ls1 = 0.f;

        #pragma unroll
        for (int kt = 0; kt < 8; kt++) {
            float p00 = fast_exp(s[2 * kt][0] - m0);
            float p01 = fast_exp(s[2 * kt][1] - m0);
            float p02 = fast_exp(s[2 * kt][2] - m1);
            float p03 = fast_exp(s[2 * kt][3] - m1);
            float p10 = fast_exp(s[2 * kt + 1][0] - m0);
            float p11 = fast_exp(s[2 * kt + 1][1] - m0);
            float p12 = fast_exp(s[2 * kt + 1][2] - m1);
            float p13 = fast_exp(s[2 * kt + 1][3] - m1);
            ls0 += p00 + p01 + p10 + p11;
            ls1 += p02 + p03 + p12 + p13;
            uint32_t ph[4], pl[4];
            split_pack(p00, p01, ph[0], pl[0]);
            split_pack(p02, p03, ph[1], pl[1]);
            split_pack(p10, p11, ph[2], pl[2]);
            split_pack(p12, p13, ph[3], pl[3]);
            #pragma unroll
            for (int dnt = 0; dnt < 8; dnt++) {
                uint32_t vh[2], vl[2];
                uint2 a = *(const uint2*)(smf + FA_VH + (size_t)(((dnt * 8 + kt) * 32 + lane) * 2) * 4);
                vh[0] = a.x; vh[1] = a.y;
                uint2 c = *(const uint2*)(smf + FA_VL + (size_t)(((dnt * 8 + kt) * 32 + lane) * 2) * 4);
                vl[0] = c.x; vl[1] = c.y;
                mma_bf16(o[dnt], ph, vh);
                mma_bf16(o[dnt], ph, vl);
                mma_bf16(o[dnt], pl, vh);
            }
        }
        ls0 += __shfl_xor_sync(0xffffffffu, ls0, 1);
        ls0 += __shfl_xor_sync(0xffffffffu, ls0, 2);
        ls1 += __shfl_xor_sync(0xffffffffu, ls1, 1);
        ls1 += __shfl_xor_sync(0xffffffffu, ls1, 2);
        l0 = l0 * al0 + ls0;
        l1 = l1 * al1 + ls1;
    }

    // ---- packed epilogue: stage hi/lo A-frags in smem, coalesced copy out ----
    __syncthreads();  // everyone done reading K/V smem
    uint32_t* sh = (uint32_t*)(smf + FA_KH);   // 4096 u32 (16KB)
    uint32_t* sl = (uint32_t*)(smf + FA_KL);
    float inv0 = 1.0f / l0, inv1 = 1.0f / l1;
    #pragma unroll
    for (int dnt = 0; dnt < 8; dnt++) {
        int kl_ = dnt * 8 + 2 * t;
        int ktl = kl_ >> 4;
        int rk = dnt & 1;
        int baseI = ((warp * 4 + ktl) * 32 + lane) * 4;
        uint32_t ph, pl;
        split_pack(o[dnt][0] * inv0, o[dnt][1] * inv0, ph, pl);
        sh[baseI + 2 * rk] = ph; sl[baseI + 2 * rk] = pl;
        split_pack(o[dnt][2] * inv1, o[dnt][3] * inv1, ph, pl);
        sh[baseI + 1 + 2 * rk] = ph; sl[baseI + 1 + 2 * rk] = pl;
    }
    __syncthreads();
    #pragma unroll
    for (int q = 0; q < 4; q++) {
        int i = q * 256 + tid;            // 0..1023 uint4 slots
        int mtl = i >> 7, jj = i & 127;
        size_t gidx = (((size_t)(b * 32 + blockIdx.x * 8 + mtl) * 64) + h * 4) * 128 + (size_t)jj * 4;
        *(uint4*)(Ohi + gidx) = ((const uint4*)sh)[i];
        *(uint4*)(Olo + gidx) = ((const uint4*)sl)[i];
    }
}

// ======================= host orchestration =======================
struct Weights {
    const float *n1g, *n1b, *n2g, *n2b, *pw, *pb, *w1, *b1, *w2, *b2;
};
struct Bufs {
    float *xb, *yb, *na, *nb;
    uint32_t *obh, *obl, *n2h, *n2l, *hbh, *hbl;
    uint32_t *pwh, *pwl, *w1h, *w1l, *w2h, *w2l;
};

static void attn_mlp_block(float* buf, float* outbuf, const float* qn, const float* kvn,
                           const Bufs& B, const Weights& W, const int* guard) {
    fattn_kernel<<<dim3(4, 64), 256, FA_SMEM>>>(qn, kvn, B.obh, B.obl, guard);
    gemm_mma<1><<<dim3(C_ / 128, R_ / 128), 256, GM_SMEM>>>(
        B.obh, B.obl, B.pwh, B.pwl, outbuf, W.pb, buf, nullptr, nullptr,
        R_, C_, C_, guard);
    lnp_kernel<<<R_ / 16, 256, 65536>>>(outbuf, B.n2h, B.n2l, W.n2g, W.n2b, guard);
    gemm_mma<2><<<dim3(HID_ / 128, R_ / 128), 256, GM_SMEM>>>(
        B.n2h, B.n2l, B.w1h, B.w1l, nullptr, W.b1, nullptr, B.hbh, B.hbl,
        R_, HID_, C_, guard);
    gemm_mma<1><<<dim3(C_ / 128, R_ / 128), 256, GM_SMEM>>>(
        B.hbh, B.hbl, B.w2h, B.w2l, outbuf, W.b2, outbuf, nullptr, nullptr,
        R_, C_, HID_, guard);
}

extern "C" void kernel_launch(void* const* d_in, const int* in_sizes, int n_in,
                              void* d_out, int out_size) {
    const float* x   = (const float*)d_in[0];
    const float* y   = (const float*)d_in[1];
    Weights W;
    W.n1g = (const float*)d_in[2];  W.n1b = (const float*)d_in[3];
    W.n2g = (const float*)d_in[4];  W.n2b = (const float*)d_in[5];
    W.pw  = (const float*)d_in[6];  W.pb  = (const float*)d_in[7];
    W.w1  = (const float*)d_in[8];  W.b1  = (const float*)d_in[9];
    W.w2  = (const float*)d_in[10]; W.b2  = (const float*)d_in[11];
    const int* flag = (const int*)d_in[12];
    float* out = (float*)d_out;

    Bufs B;
    cudaGetSymbolAddress((void**)&B.xb, g_xb);
    cudaGetSymbolAddress((void**)&B.yb, g_yb);
    cudaGetSymbolAddress((void**)&B.na, g_na);
    cudaGetSymbolAddress((void**)&B.nb, g_nb);
    cudaGetSymbolAddress((void**)&B.obh, g_obh);
    cudaGetSymbolAddress((void**)&B.obl, g_obl);
    cudaGetSymbolAddress((void**)&B.n2h, g_n2h);
    cudaGetSymbolAddress((void**)&B.n2l, g_n2l);
    cudaGetSymbolAddress((void**)&B.hbh, g_hbh);
    cudaGetSymbolAddress((void**)&B.hbl, g_hbl);
    cudaGetSymbolAddress((void**)&B.pwh, g_pwh);
    cudaGetSymbolAddress((void**)&B.pwl, g_pwl);
    cudaGetSymbolAddress((void**)&B.w1h, g_w1h);
    cudaGetSymbolAddress((void**)&B.w1l, g_w1l);
    cudaGetSymbolAddress((void**)&B.w2h, g_w2h);
    cudaGetSymbolAddress((void**)&B.w2l, g_w2l);

    cudaFuncSetAttribute(gemm_mma<1>, cudaFuncAttributeMaxDynamicSharedMemorySize, GM_SMEM);
    cudaFuncSetAttribute(gemm_mma<2>, cudaFuncAttributeMaxDynamicSharedMemorySize, GM_SMEM);
    cudaFuncSetAttribute(fattn_kernel, cudaFuncAttributeMaxDynamicSharedMemorySize, FA_SMEM);
    cudaFuncSetAttribute(lnp_kernel, cudaFuncAttributeMaxDynamicSharedMemorySize, 65536);

    // weight prep: hi/lo split + fragment pack (runs every launch; ~25us)
    pack_weight<<<512, 256>>>(W.pw, B.pwh, B.pwl, C_, C_);
    pack_weight<<<512, 256>>>(W.w1, B.w1h, B.w1l, C_, HID_);
    pack_weight<<<512, 256>>>(W.w2, B.w2h, B.w2l, HID_, C_);

    const size_t bytes = (size_t)R_ * C_ * sizeof(float);
    cudaMemcpyAsync(B.xb, x, bytes, cudaMemcpyDeviceToDevice);
    cudaMemcpyAsync(B.yb, y, bytes, cudaMemcpyDeviceToDevice);

    // Only the FINAL iteration's cross block is live: 4 gated self-blocks per
    // stream, then exactly one cross block per stream.
    for (int it = 0; it < 4; it++) {
        ln_kernel<<<R_, 256>>>(B.xb, B.na, W.n1g, W.n1b, flag);
        attn_mlp_block(B.xb, B.xb, B.na, B.na, B, W, flag);
        ln_kernel<<<R_, 256>>>(B.yb, B.na, W.n1g, W.n1b, flag);
        attn_mlp_block(B.yb, B.yb, B.na, B.na, B, W, flag);
    }

    float* ox = out;                      // x1
    float* oy = out + (size_t)R_ * C_;    // y1

    ln_kernel<<<R_, 256>>>(B.xb, B.na, W.n1g, W.n1b, nullptr);
    ln_kernel<<<R_, 256>>>(B.yb, B.nb, W.n1g, W.n1b, nullptr);
    {
        // x side: q = na, kv = nb
        fattn_kernel<<<dim3(4, 64), 256, FA_SMEM>>>(B.na, B.nb, B.obh, B.obl, nullptr);
        gemm_mma<1><<<dim3(C_ / 128, R_ / 128), 256, GM_SMEM>>>(
            B.obh, B.obl, B.pwh, B.pwl, ox, W.pb, B.xb, nullptr, nullptr,
            R_, C_, C_, nullptr);
        // y side: q = nb, kv = na
        fattn_kernel<<<dim3(4, 64), 256, FA_SMEM>>>(B.nb, B.na, B.obh, B.obl, nullptr);
        gemm_mma<1><<<dim3(C_ / 128, R_ / 128), 256, GM_SMEM>>>(
            B.obh, B.obl, B.pwh, B.pwl, oy, W.pb, B.yb, nullptr, nullptr,
            R_, C_, C_, nullptr);
        // MLP on x1
        lnp_kernel<<<R_ / 16, 256, 65536>>>(ox, B.n2h, B.n2l, W.n2g, W.n2b, nullptr);
        gemm_mma<2><<<dim3(HID_ / 128, R_ / 128), 256, GM_SMEM>>>(
            B.n2h, B.n2l, B.w1h, B.w1l, nullptr, W.b1, nullptr, B.hbh, B.hbl,
            R_, HID_, C_, nullptr);
        gemm_mma<1><<<dim3(C_ / 128, R_ / 128), 256, GM_SMEM>>>(
            B.hbh, B.hbl, B.w2h, B.w2l, ox, W.b2, ox, nullptr, nullptr,
            R_, C_, HID_, nullptr);
        // MLP on y1
        lnp_kernel<<<R_ / 16, 256, 65536>>>(oy, B.n2h, B.n2l, W.n2g, W.n2b, nullptr);
        gemm_mma<2><<<dim3(HID_ / 128, R_ / 128), 256, GM_SMEM>>>(
            B.n2h, B.n2l, B.w1h, B.w1l, nullptr, W.b1, nullptr, B.hbh, B.hbl,
            R_, HID_, C_, nullptr);
        gemm_mma<1><<<dim3(C_ / 128, R_ / 128), 256, GM_SMEM>>>(
            B.hbh, B.hbl, B.w2h, B.w2l, oy, W.b2, oy, nullptr, nullptr,
            R_, C_, HID_, nullptr);
    }
}

// round 6
// speedup vs baseline: 3.9735x; 1.1518x over previous
#include <cuda_runtime.h>
#include <cuda_bf16.h>
#include <math.h>
#include <stdint.h>

// Problem dims (fixed by the dataset)
#define B_   4
#define N_   512
#define C_   1024
#define HID_ 4096
#define NH_  16
#define D_   64
#define R_   (B_*N_)     // 2048 rows per stream
#define R2_  (2*R_)      // 4096 rows: x-stream and y-stream batched
#define EPS_ 1e-5f

// ---------------- scratch (device globals: no allocation allowed) ----------
__device__ float g_zb[R2_*C_];    // concat(x, y) residual stream
__device__ float g_na[R2_*C_];    // ln1 out (fattn input)
// packed (hi/lo, A-fragment layout) activations
__device__ uint32_t g_obh[R2_*C_/2],  g_obl[R2_*C_/2];    // fattn out -> proj A
__device__ uint32_t g_n2h[R2_*C_/2],  g_n2l[R2_*C_/2];    // ln2 out   -> fc1 A
__device__ uint32_t g_hbh[R2_*HID_/2], g_hbl[R2_*HID_/2]; // gelu out  -> fc2 A
// hi/lo-split weights, packed in mma.m16n8k16 B-fragment layout
__device__ uint32_t g_pwh[C_*C_/2],   g_pwl[C_*C_/2];
__device__ uint32_t g_w1h[C_*HID_/2], g_w1l[C_*HID_/2];
__device__ uint32_t g_w2h[HID_*C_/2], g_w2l[HID_*C_/2];

// ======================= helpers =======================
#define CP_ASYNC16(sm, gp) \
    asm volatile("cp.async.cg.shared.global [%0], [%1], 16;" :: "r"(sm), "l"(gp))
#define CP_COMMIT() asm volatile("cp.async.commit_group;" ::: "memory")
#define CP_WAIT0()  asm volatile("cp.async.wait_group 0;" ::: "memory")
#define CP_WAIT1()  asm volatile("cp.async.wait_group 1;" ::: "memory")

__device__ __forceinline__ uint32_t smem_u32(const void* p) {
    uint32_t a;
    asm("{ .reg .u64 t; cvta.to.shared.u64 t, %1; cvt.u32.u64 %0, t; }" : "=r"(a) : "l"(p));
    return a;
}

__device__ __forceinline__ void splitbf(float x, uint16_t& h, uint16_t& l) {
    __nv_bfloat16 bh = __float2bfloat16_rn(x);
    float r = x - __bfloat162float(bh);
    __nv_bfloat16 bl = __float2bfloat16_rn(r);
    h = __bfloat16_as_ushort(bh);
    l = __bfloat16_as_ushort(bl);
}
__device__ __forceinline__ uint32_t pack2(uint16_t lo16, uint16_t hi16) {
    return (uint32_t)lo16 | ((uint32_t)hi16 << 16);
}
__device__ __forceinline__ void split_pack(float a, float b, uint32_t& ph, uint32_t& pl) {
    uint16_t ha, la, hb2, lb2;
    splitbf(a, ha, la); splitbf(b, hb2, lb2);
    ph = pack2(ha, hb2); pl = pack2(la, lb2);
}

__device__ __forceinline__ void mma_bf16(float* c, const uint32_t* a, const uint32_t* b) {
    asm volatile(
        "mma.sync.aligned.m16n8k16.row.col.f32.bf16.bf16.f32 "
        "{%0,%1,%2,%3}, {%4,%5,%6,%7}, {%8,%9}, {%0,%1,%2,%3};"
        : "+f"(c[0]), "+f"(c[1]), "+f"(c[2]), "+f"(c[3])
        : "r"(a[0]), "r"(a[1]), "r"(a[2]), "r"(a[3]), "r"(b[0]), "r"(b[1]));
}

__device__ __forceinline__ float fast_exp(float x) {
    float tt = fmaxf(x * 1.4426950408889634f, -126.0f);
    float fi = floorf(tt);
    float f = tt - fi;
    float p = 0.0013333558f;
    p = fmaf(p, f, 0.0096181291f);
    p = fmaf(p, f, 0.0555041087f);
    p = fmaf(p, f, 0.2402265070f);
    p = fmaf(p, f, 0.6931471806f);
    p = fmaf(p, f, 1.0f);
    return p * __int_as_float((__float2int_rn(fi) + 127) << 23);
}

// ======================= LayerNorm (raw out, for ln1) =======================
__global__ void ln_kernel(const float* __restrict__ in, float* __restrict__ out,
                          const float* __restrict__ gm, const float* __restrict__ bt,
                          const int* guard) {
    if (guard && !guard[0]) return;
    int row = blockIdx.x;
    const float* x = in + (size_t)row * C_;
    float* y = out + (size_t)row * C_;
    float s = 0.f, ss = 0.f;
    for (int i = threadIdx.x; i < C_; i += 256) {
        float v = x[i];
        s += v; ss += v * v;
    }
    __shared__ float red[16];
    for (int o = 16; o; o >>= 1) {
        s  += __shfl_down_sync(0xffffffffu, s, o);
        ss += __shfl_down_sync(0xffffffffu, ss, o);
    }
    int wid = threadIdx.x >> 5, lid = threadIdx.x & 31;
    if (!lid) { red[wid] = s; red[wid + 8] = ss; }
    __syncthreads();
    float mean, rstd;
    {
        float a = 0.f, c2 = 0.f;
        #pragma unroll
        for (int i = 0; i < 8; i++) { a += red[i]; c2 += red[i + 8]; }
        mean = a * (1.0f / C_);
        float var = c2 * (1.0f / C_) - mean * mean;
        rstd = rsqrtf(var + EPS_);
    }
    for (int i = threadIdx.x; i < C_; i += 256) {
        y[i] = (x[i] - mean) * rstd * gm[i] + bt[i];
    }
}

// ============ LayerNorm -> packed hi/lo A-fragments (for ln2 -> fc1) =========
__global__ void __launch_bounds__(256) lnp_kernel(
    const float* __restrict__ in, uint32_t* __restrict__ outH,
    uint32_t* __restrict__ outL, const float* __restrict__ gm,
    const float* __restrict__ bt, const int* guard)
{
    if (guard && !guard[0]) return;
    extern __shared__ __align__(16) char sml[];
    uint32_t* sh = (uint32_t*)sml;
    uint32_t* sl = (uint32_t*)(sml + 32768);
    const int w = threadIdx.x >> 5, lane = threadIdx.x & 31;

    #pragma unroll
    for (int rr = 0; rr < 2; rr++) {
        const int row = blockIdx.x * 16 + w * 2 + rr;
        const float* x = in + (size_t)row * C_;
        float4 v[8];
        float s = 0.f, ss = 0.f;
        #pragma unroll
        for (int i = 0; i < 8; i++) {
            v[i] = *(const float4*)(x + i * 128 + lane * 4);
            s += v[i].x + v[i].y + v[i].z + v[i].w;
            ss += v[i].x * v[i].x + v[i].y * v[i].y + v[i].z * v[i].z + v[i].w * v[i].w;
        }
        #pragma unroll
        for (int o = 16; o; o >>= 1) {
            s  += __shfl_xor_sync(0xffffffffu, s, o);
            ss += __shfl_xor_sync(0xffffffffu, ss, o);
        }
        float mean = s * (1.0f / C_);
        float rstd = rsqrtf(ss * (1.0f / C_) - mean * mean + EPS_);
        const int ag = row & 7, m8 = (row >> 3) & 1;
        const int kin = (lane & 3) * 4;
        const int tt0 = (kin & 7) >> 1, rk = kin >> 3;
        #pragma unroll
        for (int i = 0; i < 8; i++) {
            int c = i * 128 + lane * 4;
            float4 gv = *(const float4*)(gm + c);
            float4 bv = *(const float4*)(bt + c);
            float n0 = (v[i].x - mean) * rstd * gv.x + bv.x;
            float n1 = (v[i].y - mean) * rstd * gv.y + bv.y;
            float n2 = (v[i].z - mean) * rstd * gv.z + bv.z;
            float n3 = (v[i].w - mean) * rstd * gv.w + bv.w;
            int kt = c >> 4;
            int r = m8 + 2 * rk;
            uint32_t ph, pl;
            split_pack(n0, n1, ph, pl);
            int idx0 = (kt * 32 + ag * 4 + tt0) * 4 + r;
            sh[idx0] = ph; sl[idx0] = pl;
            split_pack(n2, n3, ph, pl);
            int idx1 = (kt * 32 + ag * 4 + tt0 + 1) * 4 + r;
            sh[idx1] = ph; sl[idx1] = pl;
        }
    }
    __syncthreads();
    size_t gbase = (size_t)blockIdx.x * 8192;
    #pragma unroll
    for (int q = 0; q < 8; q++) {
        int i = q * 256 + threadIdx.x;
        *(uint4*)(outH + gbase + (size_t)i * 4) = ((const uint4*)sh)[i];
        *(uint4*)(outL + gbase + (size_t)i * 4) = ((const uint4*)sl)[i];
    }
}

// ========== weight prep: hi/lo split + pack into B-fragment layout =========
__global__ void pack_weight(const float* __restrict__ W, uint32_t* __restrict__ hiP,
                            uint32_t* __restrict__ loP, int K, int N) {
    int warp = threadIdx.x >> 5, lane = threadIdx.x & 31;
    int g = lane >> 2, t = lane & 3;
    int ktiles = K >> 4;
    int tiles = (N >> 3) * ktiles;
    for (int tile = blockIdx.x * 8 + warp; tile < tiles; tile += gridDim.x * 8) {
        int ntg = tile / ktiles, ksg = tile % ktiles;
        int n = ntg * 8 + g;
        #pragma unroll
        for (int reg = 0; reg < 2; reg++) {
            int k = ksg * 16 + 2 * t + reg * 8;
            float x0 = W[(size_t)k * N + n];
            float x1 = W[(size_t)(k + 1) * N + n];
            uint16_t h0, l0, h1, l1;
            splitbf(x0, h0, l0);
            splitbf(x1, h1, l1);
            size_t idx = ((size_t)tile * 32 + lane) * 2 + reg;
            hiP[idx] = pack2(h0, h1);
            loP[idx] = pack2(l0, l1);
        }
    }
}

// ======================= bf16-split mma GEMM (packed A + packed B) ==========
#define GM_STAGE 32768
#define GM_SMEM  (3 * GM_STAGE)

template <int EPI>
__global__ void __launch_bounds__(256) gemm_mma(
    const uint32_t* __restrict__ AhiP, const uint32_t* __restrict__ AloP,
    const uint32_t* __restrict__ BhiP, const uint32_t* __restrict__ BloP,
    float* __restrict__ Cout, const float* __restrict__ bias,
    const float* __restrict__ res,
    uint32_t* __restrict__ OutHi, uint32_t* __restrict__ OutLo,
    int M, int Nt, int K, const int* guard)
{
    if (guard && !guard[0]) return;
    extern __shared__ __align__(16) char smc[];
    const int tid = threadIdx.x;
    const int warp = tid >> 5, lane = tid & 31;
    const int g = lane >> 2, t = lane & 3;
    const int wm = warp & 1, wn = warp >> 1;
    const int bm = blockIdx.y * 128, bn = blockIdx.x * 128;
    const uint32_t sb = smem_u32(smc);

    const int NIT = K >> 5;
    const int ktiles = K >> 4;
    const int bm16 = bm >> 4, bn8 = bn >> 3;

    auto cpA = [&](int stage, int it) {
        uint32_t dstb = sb + stage * GM_STAGE;
        int kt0 = it * 2;
        #pragma unroll
        for (int q = 0; q < 2; q++) {
            int chunk = q * 256 + tid;
            int mtk = chunk >> 5, j = chunk & 31;
            int mtl = mtk >> 1, ktl = mtk & 1;
            size_t gidx = (((size_t)(bm16 + mtl) * ktiles + kt0 + ktl) * 32 + j) * 4;
            uint32_t dst = dstb + (uint32_t)(mtk * 512 + j * 16);
            CP_ASYNC16(dst, AhiP + gidx);
            CP_ASYNC16(dst + 8192u, AloP + gidx);
        }
    };
    auto cpB = [&](int stage, int it) {
        uint32_t dstb = sb + stage * GM_STAGE + 16384;
        int ksg0 = it * 2;
        #pragma unroll
        for (int q = 0; q < 2; q++) {
            int i = q * 256 + tid;
            int nt = i >> 5, j = i & 31;
            size_t srcoff = (((size_t)(bn8 + nt) * ktiles + ksg0) * 64 + (size_t)j * 4);
            uint32_t dst = dstb + (uint32_t)(nt * 512 + j * 16);
            CP_ASYNC16(dst, BhiP + srcoff);
            CP_ASYNC16(dst + 8192u, BloP + srcoff);
        }
    };

    float acc[4][4][4] = {};

    auto compute = [&](int stage) {
        char* base = smc + stage * GM_STAGE;
        #pragma unroll
        for (int ks = 0; ks < 2; ks++) {
            uint32_t ah[4][4], al[4][4], bh[4][2], bl[4][2];
            #pragma unroll
            for (int mt = 0; mt < 4; mt++) {
                uint32_t off = (uint32_t)(((wm * 4 + mt) * 2 + ks) * 32 + lane) * 16;
                uint4 v = *(const uint4*)(base + off);
                ah[mt][0] = v.x; ah[mt][1] = v.y; ah[mt][2] = v.z; ah[mt][3] = v.w;
                uint4 w = *(const uint4*)(base + 8192 + off);
                al[mt][0] = w.x; al[mt][1] = w.y; al[mt][2] = w.z; al[mt][3] = w.w;
            }
            #pragma unroll
            for (int nt = 0; nt < 4; nt++) {
                uint32_t off = 16384u + (uint32_t)(((wn * 4 + nt) * 2 + ks) * 32 + lane) * 8;
                uint2 v = *(const uint2*)(base + off);
                bh[nt][0] = v.x; bh[nt][1] = v.y;
                uint2 w = *(const uint2*)(base + 8192 + off);
                bl[nt][0] = w.x; bl[nt][1] = w.y;
            }
            #pragma unroll
            for (int mt = 0; mt < 4; mt++)
                #pragma unroll
                for (int nt = 0; nt < 4; nt++) {
                    mma_bf16(acc[mt][nt], ah[mt], bh[nt]);
                    mma_bf16(acc[mt][nt], ah[mt], bl[nt]);
                    mma_bf16(acc[mt][nt], al[mt], bh[nt]);
                }
        }
    };

    cpA(0, 0); cpB(0, 0); CP_COMMIT();
    cpA(1, 1); cpB(1, 1); CP_COMMIT();

    int st = 0;
    for (int it = 0; it < NIT; it++) {
        if (it + 1 < NIT) { CP_WAIT1(); } else { CP_WAIT0(); }
        __syncthreads();
        if (it + 2 < NIT) {
            int ns = st + 2; if (ns >= 3) ns -= 3;
            cpA(ns, it + 2); cpB(ns, it + 2); CP_COMMIT();
        }
        compute(st);
        if (++st == 3) st = 0;
    }
    __syncthreads();

    if (EPI == 1) {
        #pragma unroll
        for (int mt = 0; mt < 4; mt++) {
            #pragma unroll
            for (int nt = 0; nt < 4; nt++) {
                int row0 = bm + wm * 64 + mt * 16 + g;
                int col = bn + wn * 32 + nt * 8 + t * 2;
                float2 bv = *(const float2*)&bias[col];
                float v0 = acc[mt][nt][0] + bv.x;
                float v1 = acc[mt][nt][1] + bv.y;
                float v2 = acc[mt][nt][2] + bv.x;
                float v3 = acc[mt][nt][3] + bv.y;
                size_t i0 = (size_t)row0 * Nt + col;
                size_t i1 = (size_t)(row0 + 8) * Nt + col;
                float2 r0 = *(const float2*)&res[i0];
                float2 r1 = *(const float2*)&res[i1];
                *(float2*)&Cout[i0] = make_float2(v0 + r0.x, v1 + r0.y);
                *(float2*)&Cout[i1] = make_float2(v2 + r1.x, v3 + r1.y);
            }
        }
    } else {
        uint32_t* sh = (uint32_t*)smc;
        uint32_t* sl = (uint32_t*)(smc + 32768);
        #pragma unroll
        for (int mt = 0; mt < 4; mt++) {
            #pragma unroll
            for (int nt = 0; nt < 4; nt++) {
                int kl = wn * 32 + nt * 8 + t * 2;
                float2 bv = *(const float2*)&bias[bn + kl];
                float v0 = acc[mt][nt][0] + bv.x;
                float v1 = acc[mt][nt][1] + bv.y;
                float v2 = acc[mt][nt][2] + bv.x;
                float v3 = acc[mt][nt][3] + bv.y;
                v0 = 0.5f * v0 * (1.0f + erff(v0 * 0.70710678118654752f));
                v1 = 0.5f * v1 * (1.0f + erff(v1 * 0.70710678118654752f));
                v2 = 0.5f * v2 * (1.0f + erff(v2 * 0.70710678118654752f));
                v3 = 0.5f * v3 * (1.0f + erff(v3 * 0.70710678118654752f));
                int mtl = wm * 4 + mt;
                int ktl = kl >> 4;
                int tt = (kl & 7) >> 1;
                int rk = (kl >> 3) & 1;
                int baseI = ((mtl * 8 + ktl) * 32 + g * 4 + tt) * 4;
                uint32_t ph, pl;
                split_pack(v0, v1, ph, pl);
                sh[baseI + 2 * rk] = ph; sl[baseI + 2 * rk] = pl;
                split_pack(v2, v3, ph, pl);
                sh[baseI + 1 + 2 * rk] = ph; sl[baseI + 1 + 2 * rk] = pl;
            }
        }
        __syncthreads();
        const int ktO = Nt >> 4;
        #pragma unroll
        for (int q = 0; q < 8; q++) {
            int i = q * 256 + tid;
            int mtl = i >> 8, jj = i & 255;
            size_t gidx = (((size_t)(bm16 + mtl) * ktO + (bn >> 4)) * 128) + (size_t)jj * 4;
            *(uint4*)(OutHi + gidx) = ((const uint4*)sh)[i];
            *(uint4*)(OutLo + gidx) = ((const uint4*)sl)[i];
        }
    }
}

// ======================= fused flash attention (tensor cores) ===============
// grid (4 q-tiles, 8*NH). batch bb = blockIdx.y>>4 in 0..7 (x:0-3, y:4-7).
// KV batch = bb ^ kvxor (0 = self, 4 = cross between x and y halves).
#define FA_QH 0
#define FA_QL 16384
#define FA_KH 32768
#define FA_KL 49152
#define FA_VH 65536
#define FA_VL 81920
#define FA_SMEM 98304

__global__ void __launch_bounds__(256, 1) fattn_kernel(
    const float* __restrict__ NA, int kvxor,
    uint32_t* __restrict__ Ohi, uint32_t* __restrict__ Olo, const int* guard)
{
    if (guard && !guard[0]) return;
    extern __shared__ __align__(16) char smf[];
    const int tid = threadIdx.x, lane = tid & 31, warp = tid >> 5;
    const int g = lane >> 2, t = lane & 3;
    const int bh = blockIdx.y, b = bh >> 4, h = bh & 15;
    const int n0 = blockIdx.x * 128;
    const float* Qb = NA + (size_t)b * N_ * C_ + h * D_;
    const float* Kb = NA + (size_t)(b ^ kvxor) * N_ * C_ + h * D_;

    // ---- Q -> A-fragments (hi/lo), scaled by 1/8 ----
    {
        const int arow = tid >> 1, hf = tid & 1;
        const float* qp = Qb + (size_t)(n0 + arow) * C_ + hf * 32;
        const int mtile = arow >> 4, ag = arow & 7, arm = (arow >> 3) & 1;
        #pragma unroll
        for (int q4 = 0; q4 < 8; q4++) {
            float4 v = *(const float4*)(qp + q4 * 4);
            float xs[4] = {v.x * 0.125f, v.y * 0.125f, v.z * 0.125f, v.w * 0.125f};
            #pragma unroll
            for (int p = 0; p < 2; p++) {
                int d = hf * 32 + q4 * 4 + 2 * p;
                uint32_t ph, pl;
                split_pack(xs[2 * p], xs[2 * p + 1], ph, pl);
                int kt = d >> 4, kin = d & 15;
                int tt = (kin & 7) >> 1, rk = kin >> 3;
                uint32_t idx = (uint32_t)(((mtile * 4 + kt) * 32 + ag * 4 + tt) * 4 + (arm + 2 * rk));
                *(uint32_t*)(smf + FA_QH + idx * 4) = ph;
                *(uint32_t*)(smf + FA_QL + idx * 4) = pl;
            }
        }
    }
    __syncthreads();

    uint32_t qh[4][4], ql[4][4];
    #pragma unroll
    for (int kt = 0; kt < 4; kt++) {
        uint4 v = *(const uint4*)(smf + FA_QH + (size_t)(((warp * 4 + kt) * 32 + lane) * 4) * 4);
        qh[kt][0] = v.x; qh[kt][1] = v.y; qh[kt][2] = v.z; qh[kt][3] = v.w;
        uint4 w = *(const uint4*)(smf + FA_QL + (size_t)(((warp * 4 + kt) * 32 + lane) * 4) * 4);
        ql[kt][0] = w.x; ql[kt][1] = w.y; ql[kt][2] = w.z; ql[kt][3] = w.w;
    }

    float o[8][4] = {};
    float m0 = -1e30f, m1 = -1e30f, l0 = 0.f, l1 = 0.f;

    for (int ch = 0; ch < 4; ch++) {
        const int s0 = ch * 128;
        __syncthreads();
        // ---- K chunk -> B-frags ----
        {
            const int r = tid >> 1, hf = tid & 1;
            const float* kp = Kb + (size_t)(s0 + r) * C_ + hf * 32;
            const int ntile = r >> 3, kg = r & 7;
            #pragma unroll
            for (int q4 = 0; q4 < 8; q4++) {
                float4 v = *(const float4*)(kp + q4 * 4);
                float xs[4] = {v.x, v.y, v.z, v.w};
                #pragma unroll
                for (int p = 0; p < 2; p++) {
                    int d = hf * 32 + q4 * 4 + 2 * p;
                    uint32_t ph, pl;
                    split_pack(xs[2 * p], xs[2 * p + 1], ph, pl);
                    int kt = d >> 4;
                    int lanef = kg * 4 + ((d & 7) >> 1);
                    int reg = ((d & 15) >= 8) ? 1 : 0;
                    uint32_t idx = (uint32_t)(((ntile * 4 + kt) * 32 + lanef) * 2 + reg);
                    *(uint32_t*)(smf + FA_KH + idx * 4) = ph;
                    *(uint32_t*)(smf + FA_KL + idx * 4) = pl;
                }
            }
        }
        // ---- V chunk -> B-frags (n=d, k=s) ----
        {
            const int sp = tid & 63, dq = tid >> 6;
            const float* vp = Kb + (size_t)(s0 + 2 * sp) * C_ + dq * 16;
            #pragma unroll
            for (int q4 = 0; q4 < 4; q4++) {
                float4 a = *(const float4*)(vp + q4 * 4);
                float4 c = *(const float4*)(vp + C_ + q4 * 4);
                float as[4] = {a.x, a.y, a.z, a.w};
                float cs[4] = {c.x, c.y, c.z, c.w};
                #pragma unroll
                for (int e = 0; e < 4; e++) {
                    int d = dq * 16 + q4 * 4 + e;
                    uint32_t ph, pl;
                    split_pack(as[e], cs[e], ph, pl);
                    int dnt = d >> 3, skt = sp >> 3;
                    int lanef = (d & 7) * 4 + (sp & 3);
                    int reg = (sp >> 2) & 1;
                    uint32_t idx = (uint32_t)(((dnt * 8 + skt) * 32 + lanef) * 2 + reg);
                    *(uint32_t*)(smf + FA_VH + idx * 4) = ph;
                    *(uint32_t*)(smf + FA_VL + idx * 4) = pl;
                }
            }
        }
        __syncthreads();

        // ---- S = Q @ K^T (3-term) ----
        float s[16][4];
        #pragma unroll
        for (int nt = 0; nt < 16; nt++) { s[nt][0] = s[nt][1] = s[nt][2] = s[nt][3] = 0.f; }
        #pragma unroll
        for (int nt = 0; nt < 16; nt++) {
            #pragma unroll
            for (int kt = 0; kt < 4; kt++) {
                uint32_t kh[2], kl[2];
                uint2 a = *(const uint2*)(smf + FA_KH + (size_t)(((nt * 4 + kt) * 32 + lane) * 2) * 4);
                kh[0] = a.x; kh[1] = a.y;
                uint2 c = *(const uint2*)(smf + FA_KL + (size_t)(((nt * 4 + kt) * 32 + lane) * 2) * 4);
                kl[0] = c.x; kl[1] = c.y;
                mma_bf16(s[nt], qh[kt], kh);
                mma_bf16(s[nt], qh[kt], kl);
                mma_bf16(s[nt], ql[kt], kh);
            }
        }

        // ---- online softmax ----
        float cm0 = -1e30f, cm1 = -1e30f;
        #pragma unroll
        for (int nt = 0; nt < 16; nt++) {
            cm0 = fmaxf(cm0, fmaxf(s[nt][0], s[nt][1]));
            cm1 = fmaxf(cm1, fmaxf(s[nt][2], s[nt][3]));
        }
        cm0 = fmaxf(cm0, __shfl_xor_sync(0xffffffffu, cm0, 1));
        cm0 = fmaxf(cm0, __shfl_xor_sync(0xffffffffu, cm0, 2));
        cm1 = fmaxf(cm1, __shfl_xor_sync(0xffffffffu, cm1, 1));
        cm1 = fmaxf(cm1, __shfl_xor_sync(0xffffffffu, cm1, 2));
        float nm0 = fmaxf(m0, cm0), nm1 = fmaxf(m1, cm1);
        float al0 = fast_exp(m0 - nm0), al1 = fast_exp(m1 - nm1);
        m0 = nm0; m1 = nm1;
        #pragma unroll
        for (int dnt = 0; dnt < 8; dnt++) {
            o[dnt][0] *= al0; o[dnt][1] *= al0;
            o[dnt][2] *= al1; o[dnt][3] *= al1;
        }
        float ls0 = 0.f, ls1 = 0.f;

        #pragma unroll
        for (int kt = 0; kt < 8; kt++) {
            float p00 = fast_exp(s[2 * kt][0] - m0);
            float p01 = fast_exp(s[2 * kt][1] - m0);
            float p02 = fast_exp(s[2 * kt][2] - m1);
            float p03 = fast_exp(s[2 * kt][3] - m1);
            float p10 = fast_exp(s[2 * kt + 1][0] - m0);
            float p11 = fast_exp(s[2 * kt + 1][1] - m0);
            float p12 = fast_exp(s[2 * kt + 1][2] - m1);
            float p13 = fast_exp(s[2 * kt + 1][3] - m1);
            ls0 += p00 + p01 + p10 + p11;
            ls1 += p02 + p03 + p12 + p13;
            uint32_t ph[4], pl[4];
            split_pack(p00, p01, ph[0], pl[0]);
            split_pack(p02, p03, ph[1], pl[1]);
            split_pack(p10, p11, ph[2], pl[2]);
            split_pack(p12, p13, ph[3], pl[3]);
            #pragma unroll
            for (int dnt = 0; dnt < 8; dnt++) {
                uint32_t vh[2], vl[2];
                uint2 a = *(const uint2*)(smf + FA_VH + (size_t)(((dnt * 8 + kt) * 32 + lane) * 2) * 4);
                vh[0] = a.x; vh[1] = a.y;
                uint2 c = *(const uint2*)(smf + FA_VL + (size_t)(((dnt * 8 + kt) * 32 + lane) * 2) * 4);
                vl[0] = c.x; vl[1] = c.y;
                mma_bf16(o[dnt], ph, vh);
                mma_bf16(o[dnt], ph, vl);
                mma_bf16(o[dnt], pl, vh);
            }
        }
        ls0 += __shfl_xor_sync(0xffffffffu, ls0, 1);
        ls0 += __shfl_xor_sync(0xffffffffu, ls0, 2);
        ls1 += __shfl_xor_sync(0xffffffffu, ls1, 1);
        ls1 += __shfl_xor_sync(0xffffffffu, ls1, 2);
        l0 = l0 * al0 + ls0;
        l1 = l1 * al1 + ls1;
    }

    // ---- packed epilogue ----
    __syncthreads();
    uint32_t* sh = (uint32_t*)(smf + FA_KH);
    uint32_t* sl = (uint32_t*)(smf + FA_KL);
    float inv0 = 1.0f / l0, inv1 = 1.0f / l1;
    #pragma unroll
    for (int dnt = 0; dnt < 8; dnt++) {
        int kl_ = dnt * 8 + 2 * t;
        int ktl = kl_ >> 4;
        int rk = dnt & 1;
        int baseI = ((warp * 4 + ktl) * 32 + lane) * 4;
        uint32_t ph, pl;
        split_pack(o[dnt][0] * inv0, o[dnt][1] * inv0, ph, pl);
        sh[baseI + 2 * rk] = ph; sl[baseI + 2 * rk] = pl;
        split_pack(o[dnt][2] * inv1, o[dnt][3] * inv1, ph, pl);
        sh[baseI + 1 + 2 * rk] = ph; sl[baseI + 1 + 2 * rk] = pl;
    }
    __syncthreads();
    #pragma unroll
    for (int q = 0; q < 4; q++) {
        int i = q * 256 + tid;
        int mtl = i >> 7, jj = i & 127;
        size_t gidx = (((size_t)(b * 32 + blockIdx.x * 8 + mtl) * 64) + h * 4) * 128 + (size_t)jj * 4;
        *(uint4*)(Ohi + gidx) = ((const uint4*)sh)[i];
        *(uint4*)(Olo + gidx) = ((const uint4*)sl)[i];
    }
}

// ======================= host orchestration =======================
struct Weights {
    const float *n1g, *n1b, *n2g, *n2b, *pw, *pb, *w1, *b1, *w2, *b2;
};
struct Bufs {
    float *zb, *na;
    uint32_t *obh, *obl, *n2h, *n2l, *hbh, *hbl;
    uint32_t *pwh, *pwl, *w1h, *w1l, *w2h, *w2l;
};

// One full transformer block over the batched 4096-row stream.
// resbuf: residual input; outbuf: where the block output lands (may == resbuf)
static void block_batched(float* resbuf, float* outbuf, int kvxor,
                          const Bufs& B, const Weights& W, const int* guard) {
    ln_kernel<<<R2_, 256>>>(resbuf, B.na, W.n1g, W.n1b, guard);
    fattn_kernel<<<dim3(4, 8 * NH_), 256, FA_SMEM>>>(B.na, kvxor, B.obh, B.obl, guard);
    gemm_mma<1><<<dim3(C_ / 128, R2_ / 128), 256, GM_SMEM>>>(
        B.obh, B.obl, B.pwh, B.pwl, outbuf, W.pb, resbuf, nullptr, nullptr,
        R2_, C_, C_, guard);
    lnp_kernel<<<R2_ / 16, 256, 65536>>>(outbuf, B.n2h, B.n2l, W.n2g, W.n2b, guard);
    gemm_mma<2><<<dim3(HID_ / 128, R2_ / 128), 256, GM_SMEM>>>(
        B.n2h, B.n2l, B.w1h, B.w1l, nullptr, W.b1, nullptr, B.hbh, B.hbl,
        R2_, HID_, C_, guard);
    gemm_mma<1><<<dim3(C_ / 128, R2_ / 128), 256, GM_SMEM>>>(
        B.hbh, B.hbl, B.w2h, B.w2l, outbuf, W.b2, outbuf, nullptr, nullptr,
        R2_, C_, HID_, guard);
}

extern "C" void kernel_launch(void* const* d_in, const int* in_sizes, int n_in,
                              void* d_out, int out_size) {
    const float* x   = (const float*)d_in[0];
    const float* y   = (const float*)d_in[1];
    Weights W;
    W.n1g = (const float*)d_in[2];  W.n1b = (const float*)d_in[3];
    W.n2g = (const float*)d_in[4];  W.n2b = (const float*)d_in[5];
    W.pw  = (const float*)d_in[6];  W.pb  = (const float*)d_in[7];
    W.w1  = (const float*)d_in[8];  W.b1  = (const float*)d_in[9];
    W.w2  = (const float*)d_in[10]; W.b2  = (const float*)d_in[11];
    const int* flag = (const int*)d_in[12];
    float* out = (float*)d_out;    // 4096 x 1024 = concat(x1, y1)

    Bufs B;
    cudaGetSymbolAddress((void**)&B.zb, g_zb);
    cudaGetSymbolAddress((void**)&B.na, g_na);
    cudaGetSymbolAddress((void**)&B.obh, g_obh);
    cudaGetSymbolAddress((void**)&B.obl, g_obl);
    cudaGetSymbolAddress((void**)&B.n2h, g_n2h);
    cudaGetSymbolAddress((void**)&B.n2l, g_n2l);
    cudaGetSymbolAddress((void**)&B.hbh, g_hbh);
    cudaGetSymbolAddress((void**)&B.hbl, g_hbl);
    cudaGetSymbolAddress((void**)&B.pwh, g_pwh);
    cudaGetSymbolAddress((void**)&B.pwl, g_pwl);
    cudaGetSymbolAddress((void**)&B.w1h, g_w1h);
    cudaGetSymbolAddress((void**)&B.w1l, g_w1l);
    cudaGetSymbolAddress((void**)&B.w2h, g_w2h);
    cudaGetSymbolAddress((void**)&B.w2l, g_w2l);

    cudaFuncSetAttribute(gemm_mma<1>, cudaFuncAttributeMaxDynamicSharedMemorySize, GM_SMEM);
    cudaFuncSetAttribute(gemm_mma<2>, cudaFuncAttributeMaxDynamicSharedMemorySize, GM_SMEM);
    cudaFuncSetAttribute(fattn_kernel, cudaFuncAttributeMaxDynamicSharedMemorySize, FA_SMEM);
    cudaFuncSetAttribute(lnp_kernel, cudaFuncAttributeMaxDynamicSharedMemorySize, 65536);

    // weight prep (runs every launch; ~25us)
    pack_weight<<<512, 256>>>(W.pw, B.pwh, B.pwl, C_, C_);
    pack_weight<<<512, 256>>>(W.w1, B.w1h, B.w1l, C_, HID_);
    pack_weight<<<512, 256>>>(W.w2, B.w2h, B.w2l, HID_, C_);

    const size_t bytes = (size_t)R_ * C_ * sizeof(float);
    cudaMemcpyAsync(B.zb, x, bytes, cudaMemcpyDeviceToDevice);
    cudaMemcpyAsync(B.zb + (size_t)R_ * C_, y, bytes, cudaMemcpyDeviceToDevice);

    // x and y self-chains are independent with shared weights -> batched as
    // 8 "batches" (x:0-3, y:4-7). Only the FINAL iteration's cross block is
    // live: 4 gated self blocks, then one cross block (kv from opposite half).
    for (int it = 0; it < 4; it++) {
        block_batched(B.zb, B.zb, 0, B, W, flag);
    }
    // cross block: q from own half, kv from opposite half; output -> d_out
    block_batched(B.zb, out, 4, B, W, nullptr);
}